// round 1
// baseline (speedup 1.0000x reference)
#include <cuda_runtime.h>
#include <math.h>

// ---------------------------------------------------------------------------
// FouriDecoderBlock: B=4, S=2048, D=512, H=4, MID=2048, fp32.
//
// fft2 real part via DFT matmuls:
//   xf = C_S @ (x @ C_D) - S_S @ (x @ S_D),  C/S symmetric cos/sin matrices.
// Then linear-attention (softmax over heads), Wo, FFN with SELU, 3 LNs.
// Everything is GEMM (single tiled fp32 SIMT kernel) + cheap elementwise.
// ---------------------------------------------------------------------------

static constexpr int Dm  = 512;
static constexpr int Hn  = 4;
static constexpr int MIDm = 2048;
static constexpr int Bm  = 4;
static constexpr int Sm  = 2048;
static constexpr int BSm = Bm * Sm;                    // 8192
static constexpr long long BSDm = (long long)BSm * Dm; // 4194304

// ---- scratch (static __device__; no allocations anywhere) ----
__device__ float g_CS[Sm * Sm];
__device__ float g_SS[Sm * Sm];
__device__ float g_CD[Dm * Dm];
__device__ float g_SD[Dm * Dm];
__device__ float g_t1[BSm * Dm];
__device__ float g_t2[BSm * Dm];
__device__ float g_xf[BSm * Dm];
__device__ float g_xd[BSm * Dm];
__device__ float g_qs[Hn * BSm * Dm];   // layout [h][b][s][d]
__device__ float g_ks[Hn * BSm * Dm];
__device__ float g_vs[Hn * BSm * Dm];
__device__ float g_gc[Hn * Bm * Dm * Dm];  // [z=h*B+b][d][e]
__device__ float g_out[Hn * BSm * Dm];     // [z][s][d]
__device__ float g_operm[Hn * BSm * Dm];   // [b*S+s][d*H+h]
__device__ float g_attn[BSm * Dm];
__device__ float g_x2[BSm * Dm];
__device__ float g_mid[BSm * MIDm];
__device__ float g_ff[BSm * Dm];

// ---------------------------------------------------------------------------
// DFT matrix init: C[i,j] = cos(2*pi*((i*j) mod N)/N), S likewise with sin.
// ---------------------------------------------------------------------------
__global__ void init_dft(float* __restrict__ Cm, float* __restrict__ Smat, int N) {
    long long idx = (long long)blockIdx.x * blockDim.x + threadIdx.x;
    long long total = (long long)N * N;
    if (idx >= total) return;
    int i = (int)(idx / N);
    int j = (int)(idx % N);
    int p = (int)(((long long)i * j) % N);
    float x = 2.0f * (float)p / (float)N;  // in [0,2)
    float s, c;
    sincospif(x, &s, &c);
    Cm[idx] = c;
    Smat[idx] = s;
}

// ---------------------------------------------------------------------------
// Generic batched fp32 GEMM.
//   C[z] = alpha * opA(A[z]) @ B[z] + beta * C[z] (+ bias[z][n]) (+ SELU)
// NN:  A[m*lda+k];  TN (TRANS_A): A[k*lda+m]  (i.e. C = A^T B)
// Tiles: BM=128, BN=64, BK=16; 256 threads; 8x4 per thread.
// All M,N,K here are multiples of the tile sizes -> no bounds checks.
// ---------------------------------------------------------------------------
__device__ __forceinline__ float selu_f(float x) {
    const float sc = 1.0507009873554805f;
    const float al = 1.6732632423543772f;
    return x > 0.f ? sc * x : sc * al * (expf(x) - 1.f);
}

template <bool TRANS_A, int ACT>
__global__ __launch_bounds__(256) void gemm_kernel(
    const float* __restrict__ A, const float* __restrict__ Bp, float* __restrict__ C,
    int M, int N, int K, int lda, int ldb, int ldc,
    long long sA, long long sB, long long sC,
    const float* __restrict__ bias, int sBias,
    float alpha, float beta)
{
    constexpr int BM = 128, BN = 64, BK = 16;
    __shared__ float Asm[BK][BM + 4];
    __shared__ float Bsm[BK][BN + 4];

    const int tid = threadIdx.x;
    const int tx = tid & 15;    // 0..15 -> 4 cols each
    const int ty = tid >> 4;    // 0..15 -> 8 rows each
    const int z = blockIdx.z;

    const float* Ab = A + (long long)z * sA;
    const float* Bb = Bp + (long long)z * sB;
    float* Cb = C + (long long)z * sC;

    const int m0 = blockIdx.y * BM;
    const int n0 = blockIdx.x * BN;

    float acc[8][4];
#pragma unroll
    for (int i = 0; i < 8; i++)
#pragma unroll
        for (int j = 0; j < 4; j++) acc[i][j] = 0.f;

    for (int k0 = 0; k0 < K; k0 += BK) {
        if (TRANS_A) {
            // A tile is [BK][BM], contiguous along m
#pragma unroll
            for (int i = 0; i < 2; i++) {
                int q = tid + i * 256;        // 512 float4 total
                int kr = q >> 5;              // 0..15
                int mq = (q & 31) * 4;        // 0..124
                float4 v = *(const float4*)(Ab + (long long)(k0 + kr) * lda + m0 + mq);
                *(float4*)&Asm[kr][mq] = v;
            }
        } else {
            // A tile is [BM][BK], contiguous along k; transpose into Asm
#pragma unroll
            for (int i = 0; i < 2; i++) {
                int q = tid + i * 256;
                int row = q >> 2;             // 0..127
                int kq = (q & 3) * 4;         // 0,4,8,12
                float4 v = *(const float4*)(Ab + (long long)(m0 + row) * lda + k0 + kq);
                Asm[kq + 0][row] = v.x;
                Asm[kq + 1][row] = v.y;
                Asm[kq + 2][row] = v.z;
                Asm[kq + 3][row] = v.w;
            }
        }
        {
            int kr = tid >> 4;                // 0..15
            int nq = (tid & 15) * 4;          // 0..60
            float4 v = *(const float4*)(Bb + (long long)(k0 + kr) * ldb + n0 + nq);
            *(float4*)&Bsm[kr][nq] = v;
        }
        __syncthreads();

#pragma unroll
        for (int k = 0; k < BK; k++) {
            float4 b0 = *(const float4*)&Bsm[k][tx * 4];
            float4 a0 = *(const float4*)&Asm[k][ty * 8];
            float4 a1 = *(const float4*)&Asm[k][ty * 8 + 4];
            float av[8] = {a0.x, a0.y, a0.z, a0.w, a1.x, a1.y, a1.z, a1.w};
            float bv[4] = {b0.x, b0.y, b0.z, b0.w};
#pragma unroll
            for (int i = 0; i < 8; i++)
#pragma unroll
                for (int j = 0; j < 4; j++)
                    acc[i][j] = fmaf(av[i], bv[j], acc[i][j]);
        }
        __syncthreads();
    }

    float4 bb = make_float4(0.f, 0.f, 0.f, 0.f);
    if (bias) {
        const float* bp = bias + (long long)z * sBias;
        bb = *(const float4*)(bp + n0 + tx * 4);
    }
#pragma unroll
    for (int i = 0; i < 8; i++) {
        long long off = (long long)(m0 + ty * 8 + i) * ldc + n0 + tx * 4;
        float4 o;
        o.x = acc[i][0] * alpha;
        o.y = acc[i][1] * alpha;
        o.z = acc[i][2] * alpha;
        o.w = acc[i][3] * alpha;
        if (beta != 0.f) {
            float4 p = *(const float4*)(Cb + off);
            o.x = fmaf(beta, p.x, o.x);
            o.y = fmaf(beta, p.y, o.y);
            o.z = fmaf(beta, p.z, o.z);
            o.w = fmaf(beta, p.w, o.w);
        }
        o.x += bb.x; o.y += bb.y; o.z += bb.z; o.w += bb.w;
        if (ACT == 1) {
            o.x = selu_f(o.x); o.y = selu_f(o.y);
            o.z = selu_f(o.z); o.w = selu_f(o.w);
        }
        *(float4*)(Cb + off) = o;
    }
}

// ---------------------------------------------------------------------------
// LayerNorm over last dim (D=512) of (a + b), 128 threads x float4 per row.
// Two-pass (mean, then centered variance) for numerical safety (FFT rows are big).
// ---------------------------------------------------------------------------
__global__ void ln_kernel(const float* __restrict__ a, const float* __restrict__ bres,
                          const float* __restrict__ g, const float* __restrict__ be,
                          float* __restrict__ out)
{
    __shared__ float red[4];
    long long row = blockIdx.x;
    int t = threadIdx.x;  // 128

    float4 va = ((const float4*)(a + row * Dm))[t];
    float4 vb = ((const float4*)(bres + row * Dm))[t];
    float4 v = make_float4(va.x + vb.x, va.y + vb.y, va.z + vb.z, va.w + vb.w);

    float s = v.x + v.y + v.z + v.w;
#pragma unroll
    for (int o = 16; o > 0; o >>= 1) s += __shfl_xor_sync(0xffffffffu, s, o);
    if ((t & 31) == 0) red[t >> 5] = s;
    __syncthreads();
    float mu = (red[0] + red[1] + red[2] + red[3]) * (1.f / (float)Dm);
    __syncthreads();

    float dx0 = v.x - mu, dx1 = v.y - mu, dx2 = v.z - mu, dx3 = v.w - mu;
    float q = dx0 * dx0 + dx1 * dx1 + dx2 * dx2 + dx3 * dx3;
#pragma unroll
    for (int o = 16; o > 0; o >>= 1) q += __shfl_xor_sync(0xffffffffu, q, o);
    if ((t & 31) == 0) red[t >> 5] = q;
    __syncthreads();
    float var = (red[0] + red[1] + red[2] + red[3]) * (1.f / (float)Dm);
    float rstd = rsqrtf(var + 1e-5f);

    float4 vg = ((const float4*)g)[t];
    float4 vbe = ((const float4*)be)[t];
    float4 o4;
    o4.x = fmaf(vg.x, dx0 * rstd, vbe.x);
    o4.y = fmaf(vg.y, dx1 * rstd, vbe.y);
    o4.z = fmaf(vg.z, dx2 * rstd, vbe.z);
    o4.w = fmaf(vg.w, dx3 * rstd, vbe.w);
    ((float4*)(out + row * Dm))[t] = o4;
}

// ---------------------------------------------------------------------------
// Softmax over the H=4 head axis. p layout [h][b][s][d], stride BSDm per head.
// ---------------------------------------------------------------------------
__global__ void softmax_heads(float* __restrict__ p) {
    long long i = (long long)blockIdx.x * blockDim.x + threadIdx.x;
    if (i >= BSDm) return;
    float v0 = p[i];
    float v1 = p[i + BSDm];
    float v2 = p[i + 2 * BSDm];
    float v3 = p[i + 3 * BSDm];
    float m = fmaxf(fmaxf(v0, v1), fmaxf(v2, v3));
    float e0 = expf(v0 - m), e1 = expf(v1 - m), e2 = expf(v2 - m), e3 = expf(v3 - m);
    float r = 1.f / (e0 + e1 + e2 + e3);
    p[i] = e0 * r;
    p[i + BSDm] = e1 * r;
    p[i + 2 * BSDm] = e2 * r;
    p[i + 3 * BSDm] = e3 * r;
}

// ---------------------------------------------------------------------------
// Rearrange 'b h s d -> b s (d h)': dst[(b*S+s)*(D*H) + d*H + h] = src[((h*B+b)*S+s)*D + d]
// ---------------------------------------------------------------------------
__global__ void permute_out(const float* __restrict__ src, float* __restrict__ dst) {
    long long o = (long long)blockIdx.x * blockDim.x + threadIdx.x;
    const long long total = BSDm * Hn;
    if (o >= total) return;
    int h = (int)(o & 3);
    long long r = o >> 2;
    int d = (int)(r & (Dm - 1));
    long long m = r >> 9;                 // b*S + s
    long long b = m >> 11;                // S = 2048
    long long srow = m & (Sm - 1);
    dst[o] = src[(((long long)h * Bm + b) * Sm + srow) * Dm + d];
}

// ---------------------------------------------------------------------------
// Host side
// ---------------------------------------------------------------------------
static void launch_gemm(bool transA, int act,
                        const float* A, const float* B, float* C,
                        int M, int N, int K, int lda, int ldb, int ldc,
                        long long sA, long long sB, long long sC, int batch,
                        const float* bias, int sBias, float alpha, float beta)
{
    dim3 grid(N / 64, M / 128, batch), block(256);
    if (transA) {
        if (act) gemm_kernel<true, 1><<<grid, block>>>(A, B, C, M, N, K, lda, ldb, ldc, sA, sB, sC, bias, sBias, alpha, beta);
        else     gemm_kernel<true, 0><<<grid, block>>>(A, B, C, M, N, K, lda, ldb, ldc, sA, sB, sC, bias, sBias, alpha, beta);
    } else {
        if (act) gemm_kernel<false, 1><<<grid, block>>>(A, B, C, M, N, K, lda, ldb, ldc, sA, sB, sC, bias, sBias, alpha, beta);
        else     gemm_kernel<false, 0><<<grid, block>>>(A, B, C, M, N, K, lda, ldb, ldc, sA, sB, sC, bias, sBias, alpha, beta);
    }
}

extern "C" void kernel_launch(void* const* d_in, const int* in_sizes, int n_in,
                              void* d_out, int out_size)
{
    const float* x_enc = (const float*)d_in[0];
    const float* x_dec = (const float*)d_in[1];
    const float* Wq   = (const float*)d_in[2];
    const float* bq   = (const float*)d_in[3];
    const float* Wk   = (const float*)d_in[4];
    const float* bk   = (const float*)d_in[5];
    const float* Wv   = (const float*)d_in[6];
    const float* bv   = (const float*)d_in[7];
    const float* Wo   = (const float*)d_in[8];
    const float* bo   = (const float*)d_in[9];
    const float* ln1g = (const float*)d_in[10];
    const float* ln1b = (const float*)d_in[11];
    const float* ln2g = (const float*)d_in[12];
    const float* ln2b = (const float*)d_in[13];
    const float* W1   = (const float*)d_in[14];
    const float* b1   = (const float*)d_in[15];
    const float* W2   = (const float*)d_in[16];
    const float* b2   = (const float*)d_in[17];
    const float* ln3g = (const float*)d_in[18];
    const float* ln3b = (const float*)d_in[19];
    float* outp = (float*)d_out;

    void* p;
    cudaGetSymbolAddress(&p, g_CS);   float* CSp  = (float*)p;
    cudaGetSymbolAddress(&p, g_SS);   float* SSp  = (float*)p;
    cudaGetSymbolAddress(&p, g_CD);   float* CDp  = (float*)p;
    cudaGetSymbolAddress(&p, g_SD);   float* SDp  = (float*)p;
    cudaGetSymbolAddress(&p, g_t1);   float* t1p  = (float*)p;
    cudaGetSymbolAddress(&p, g_t2);   float* t2p  = (float*)p;
    cudaGetSymbolAddress(&p, g_xf);   float* xfp  = (float*)p;
    cudaGetSymbolAddress(&p, g_xd);   float* xdp  = (float*)p;
    cudaGetSymbolAddress(&p, g_qs);   float* qsp  = (float*)p;
    cudaGetSymbolAddress(&p, g_ks);   float* ksp  = (float*)p;
    cudaGetSymbolAddress(&p, g_vs);   float* vsp  = (float*)p;
    cudaGetSymbolAddress(&p, g_gc);   float* gcp  = (float*)p;
    cudaGetSymbolAddress(&p, g_out);  float* outb = (float*)p;
    cudaGetSymbolAddress(&p, g_operm);float* operm= (float*)p;
    cudaGetSymbolAddress(&p, g_attn); float* attnp= (float*)p;
    cudaGetSymbolAddress(&p, g_x2);   float* x2p  = (float*)p;
    cudaGetSymbolAddress(&p, g_mid);  float* midp = (float*)p;
    cudaGetSymbolAddress(&p, g_ff);   float* ffp  = (float*)p;

    const long long SD_ = (long long)Sm * Dm;   // per-(b or z) stride 1048576
    const long long DD_ = (long long)Dm * Dm;   // 262144

    // 0) DFT matrices
    init_dft<<<(Sm * Sm + 255) / 256, 256>>>(CSp, SSp, Sm);
    init_dft<<<(Dm * Dm + 255) / 256, 256>>>(CDp, SDp, Dm);

    // 1) t1 = x_dec @ C_D ; t2 = x_dec @ S_D   (M=8192, N=K=512)
    launch_gemm(false, 0, x_dec, CDp, t1p, BSm, Dm, Dm, Dm, Dm, Dm, 0, 0, 0, 1, nullptr, 0, 1.f, 0.f);
    launch_gemm(false, 0, x_dec, SDp, t2p, BSm, Dm, Dm, Dm, Dm, Dm, 0, 0, 0, 1, nullptr, 0, 1.f, 0.f);

    // 2) xf = C_S @ t1 - S_S @ t2   (per-batch, M=2048, N=512, K=2048)
    launch_gemm(false, 0, CSp, t1p, xfp, Sm, Dm, Sm, Sm, Dm, Dm, 0, SD_, SD_, Bm, nullptr, 0, 1.f, 0.f);
    launch_gemm(false, 0, SSp, t2p, xfp, Sm, Dm, Sm, Sm, Dm, Dm, 0, SD_, SD_, Bm, nullptr, 0, -1.f, 1.f);

    // 3) xd = LN1(x_dec + xf)
    ln_kernel<<<BSm, 128>>>(x_dec, xfp, ln1g, ln1b, xdp);

    // 4) per-head projections (batched over h), layout [h][b][s][d]
    launch_gemm(false, 0, xdp,   Wq, qsp, BSm, Dm, Dm, Dm, Dm, Dm, 0, DD_, BSDm, Hn, bq, Dm, 1.f, 0.f);
    launch_gemm(false, 0, x_enc, Wk, ksp, BSm, Dm, Dm, Dm, Dm, Dm, 0, DD_, BSDm, Hn, bk, Dm, 1.f, 0.f);
    launch_gemm(false, 0, x_enc, Wv, vsp, BSm, Dm, Dm, Dm, Dm, Dm, 0, DD_, BSDm, Hn, bv, Dm, 1.f, 0.f);

    // 5) softmax over heads (q and k)
    softmax_heads<<<(int)((BSDm + 255) / 256), 256>>>(qsp);
    softmax_heads<<<(int)((BSDm + 255) / 256), 256>>>(ksp);

    // 6) gc[z] = ks[z]^T @ vs[z]   (z = h*B+b; M=N=512, K=2048)
    launch_gemm(true, 0, ksp, vsp, gcp, Dm, Dm, Sm, Dm, Dm, Dm, SD_, SD_, DD_, Hn * Bm, nullptr, 0, 1.f, 0.f);

    // 7) out[z] = qs[z] @ gc[z]    (M=2048, N=512, K=512)
    launch_gemm(false, 0, qsp, gcp, outb, Sm, Dm, Dm, Dm, Dm, Dm, SD_, DD_, SD_, Hn * Bm, nullptr, 0, 1.f, 0.f);

    // 8) rearrange b h s d -> b s (d h)
    permute_out<<<(int)((BSDm * Hn + 255) / 256), 256>>>(outb, operm);

    // 9) attn = operm @ Wo + bo   (M=8192, N=512, K=2048)
    launch_gemm(false, 0, operm, Wo, attnp, BSm, Dm, Dm * Hn, Dm * Hn, Dm, Dm, 0, 0, 0, 1, bo, 0, 1.f, 0.f);

    // 10) x2 = LN2(xd + attn)
    ln_kernel<<<BSm, 128>>>(xdp, attnp, ln2g, ln2b, x2p);

    // 11) mid = selu(x2 @ W1 + b1)  (M=8192, N=2048, K=512)
    launch_gemm(false, 1, x2p, W1, midp, BSm, MIDm, Dm, Dm, MIDm, MIDm, 0, 0, 0, 1, b1, 0, 1.f, 0.f);

    // 12) ff = mid @ W2 + b2        (M=8192, N=512, K=2048)
    launch_gemm(false, 0, midp, W2, ffp, BSm, Dm, MIDm, MIDm, Dm, Dm, 0, 0, 0, 1, b2, 0, 1.f, 0.f);

    // 13) out = LN3(x2 + ff)
    ln_kernel<<<BSm, 128>>>(x2p, ffp, ln3g, ln3b, outp);
}

// round 3
// speedup vs baseline: 1.5354x; 1.5354x over previous
#include <cuda_runtime.h>
#include <cuda_bf16.h>
#include <math.h>
#include <stdint.h>

typedef __nv_bfloat16 bf16;

static constexpr int Dm = 512, Hn = 4, MIDm = 2048, Bm = 4, Sm = 2048;
static constexpr int BSm = Bm * Sm;                      // 8192
static constexpr long long BSD = (long long)BSm * Dm;    // 4194304
static constexpr long long SD  = (long long)Sm * Dm;     // 1048576
static constexpr long long DD  = (long long)Dm * Dm;     // 262144

// ---------------------------------------------------------------------------
// Static device scratch (no allocations anywhere)
// ---------------------------------------------------------------------------
__device__ bf16 g_CSh[4194304], g_CSl[4194304];          // cos DFT (S)
__device__ bf16 g_SSh[4194304], g_SSl[4194304];          // NEGATED sin DFT (S)
__device__ bf16 g_BDh[524288],  g_BDl[524288];           // [CD ; SD] as [1024,512]
__device__ bf16 g_xdh[4194304], g_xdl[4194304];          // x_dec split
__device__ bf16 g_xeh[4194304], g_xel[4194304];          // x_enc split
__device__ float g_t12[8388608];                         // [8192,1024]
__device__ bf16 g_t12Th[8388608], g_t12Tl[8388608];      // [4][1024,2048]
__device__ float g_xf[4194304];
__device__ float g_xd[4194304];
__device__ bf16 g_xdsh[4194304], g_xdsl[4194304];        // LN1 out split
__device__ float g_qs[16777216], g_ks[16777216], g_vs[16777216];  // [h][b,s,d]
__device__ bf16 g_qsh[16777216], g_qsl[16777216];
__device__ bf16 g_ksTh[16777216], g_ksTl[16777216];      // [z][D,S]
__device__ bf16 g_vsTh[16777216], g_vsTl[16777216];      // [z][D,S]
__device__ float g_gc[4194304];                          // [16][512,512]
__device__ bf16 g_gcTh[4194304], g_gcTl[4194304];
__device__ float g_outb[16777216];                       // [z][s,d]
__device__ bf16 g_oph[16777216], g_opl[16777216];        // operm split [8192,2048]
__device__ bf16 g_WqTh[1048576], g_WqTl[1048576];
__device__ bf16 g_WkTh[1048576], g_WkTl[1048576];
__device__ bf16 g_WvTh[1048576], g_WvTl[1048576];
__device__ bf16 g_WoTh[1048576], g_WoTl[1048576];        // [512,2048]
__device__ bf16 g_W1Th[1048576], g_W1Tl[1048576];        // [2048,512]
__device__ bf16 g_W2Th[1048576], g_W2Tl[1048576];        // [512,2048]
__device__ float g_attn[4194304];
__device__ float g_x2[4194304];
__device__ bf16 g_x2h[4194304], g_x2l[4194304];
__device__ bf16 g_midh[16777216], g_midl[16777216];      // [8192,2048]
__device__ float g_ff[4194304];

// ---------------------------------------------------------------------------
// Helpers
// ---------------------------------------------------------------------------
__device__ __forceinline__ uint32_t smem_u32(const void* p) {
    uint32_t a;
    asm("{ .reg .u64 t; cvta.to.shared.u64 t, %1; cvt.u32.u64 %0, t; }" : "=r"(a) : "l"(p));
    return a;
}
__device__ __forceinline__ float selu_f(float x) {
    const float sc = 1.0507009873554805f, al = 1.6732632423543772f;
    return x > 0.f ? sc * x : sc * al * (expf(x) - 1.f);
}
__device__ __forceinline__ void split2(float x, bf16& h, bf16& l) {
    h = __float2bfloat16(x);
    l = __float2bfloat16(x - __bfloat162float(h));
}
__device__ __forceinline__ uint32_t pack_bf16(float a, float b) {
    __nv_bfloat162 v = __floats2bfloat162_rn(a, b);
    return *reinterpret_cast<uint32_t*>(&v);
}

#define LDSM_X4(r0, r1, r2, r3, addr) \
    asm volatile("ldmatrix.sync.aligned.m8n8.x4.shared.b16 {%0,%1,%2,%3}, [%4];" \
        : "=r"(r0), "=r"(r1), "=r"(r2), "=r"(r3) : "r"(addr))

#define MMA_BF16(d, a, b0, b1) \
    asm volatile("mma.sync.aligned.m16n8k16.row.col.f32.bf16.bf16.f32 " \
        "{%0,%1,%2,%3}, {%4,%5,%6,%7}, {%8,%9}, {%0,%1,%2,%3};" \
        : "+f"((d)[0]), "+f"((d)[1]), "+f"((d)[2]), "+f"((d)[3]) \
        : "r"((a)[0]), "r"((a)[1]), "r"((a)[2]), "r"((a)[3]), "r"(b0), "r"(b1))

// ---------------------------------------------------------------------------
// HMMA GEMM: C[z] = sum_p A_p[z] @ B_p[z]^T (+bias)(+SELU)(fp32 or bf16-split)
// A_p: [M,K] bf16 row-major; B_p: [N,K] bf16 row-major (B^T layout).
// Block 128x128, 8 warps (2x4), warp tile 64x32, mma.m16n8k16, BK=32.
// All M,N,K multiples of 128/128/32; no bounds checks.
// ---------------------------------------------------------------------------
struct TcPasses { const bf16* A[6]; const bf16* B[6]; };

template <int ACT, int SPLIT>
__global__ __launch_bounds__(256, 2) void mma_gemm(
    TcPasses P, int npass,
    float* __restrict__ C, bf16* __restrict__ Chi, bf16* __restrict__ Clo,
    int K, int lda, int ldb, int ldc,
    long long sA, long long sB, long long sC,
    const float* __restrict__ bias, int sBias)
{
    constexpr int BK = 32;
    constexpr int LDS = BK + 8;   // 40 elements (80B rows, conflict-free ldmatrix)
    __shared__ bf16 As[2][128 * LDS];
    __shared__ bf16 Bs[2][128 * LDS];
    __shared__ float bias_s[128];

    const int tid = threadIdx.x;
    const int lane = tid & 31;
    const int wid = tid >> 5;
    const int wm = (wid & 1) * 64;    // warp m offset in block
    const int wn = (wid >> 1) * 32;   // warp n offset in block
    const int z = blockIdx.z;
    const int m0 = blockIdx.y * 128, n0 = blockIdx.x * 128;

    if (tid < 128) bias_s[tid] = bias ? bias[(long long)z * sBias + n0 + tid] : 0.f;

    float acc[4][4][4];
#pragma unroll
    for (int i = 0; i < 4; i++)
#pragma unroll
        for (int j = 0; j < 4; j++)
#pragma unroll
            for (int k = 0; k < 4; k++) acc[i][j][k] = 0.f;

    const int cpp = K / BK;
    const int total = npass * cpp;

    // global load mapping: row = tid>>1 (0..127), col = (tid&1)*16 + {0,8}
    const int lrow = tid >> 1;
    const int lcol = (tid & 1) * 16;

    uint4 ra0, ra1, rb0, rb1;
    auto loadG = [&](int c) {
        int p = c / cpp;
        int k0 = (c - p * cpp) * BK;
        const bf16* Ab = P.A[p] + (long long)z * sA + (long long)(m0 + lrow) * lda + k0 + lcol;
        const bf16* Bb = P.B[p] + (long long)z * sB + (long long)(n0 + lrow) * ldb + k0 + lcol;
        ra0 = *(const uint4*)Ab;       ra1 = *(const uint4*)(Ab + 8);
        rb0 = *(const uint4*)Bb;       rb1 = *(const uint4*)(Bb + 8);
    };
    auto storeS = [&](int buf) {
        *(uint4*)&As[buf][lrow * LDS + lcol]     = ra0;
        *(uint4*)&As[buf][lrow * LDS + lcol + 8] = ra1;
        *(uint4*)&Bs[buf][lrow * LDS + lcol]     = rb0;
        *(uint4*)&Bs[buf][lrow * LDS + lcol + 8] = rb1;
    };

    // ldmatrix shared addresses (per lane), as byte offsets into each buffer
    const uint32_t aBase0 = smem_u32(&As[0][0]);
    const uint32_t aBase1 = smem_u32(&As[1][0]);
    const uint32_t bBase0 = smem_u32(&Bs[0][0]);
    const uint32_t bBase1 = smem_u32(&Bs[1][0]);
    const int lrow16 = lane & 15;     // row within 16-row group
    const int lhalf = lane >> 4;      // 0/1 -> col halves (+8 elements)

    loadG(0);
    storeS(0);
    __syncthreads();

    for (int c = 0; c < total; c++) {
        if (c + 1 < total) loadG(c + 1);
        const int buf = c & 1;
        const uint32_t aB = buf ? aBase1 : aBase0;
        const uint32_t bB = buf ? bBase1 : bBase0;
#pragma unroll
        for (int ks = 0; ks < 2; ks++) {
            uint32_t af[4][4];
#pragma unroll
            for (int mi = 0; mi < 4; mi++) {
                uint32_t addr = aB + (uint32_t)(((wm + mi * 16 + lrow16) * LDS
                                                + ks * 16 + lhalf * 8) * 2);
                LDSM_X4(af[mi][0], af[mi][1], af[mi][2], af[mi][3], addr);
            }
            uint32_t bfr[2][4];
#pragma unroll
            for (int nj = 0; nj < 2; nj++) {
                uint32_t addr = bB + (uint32_t)(((wn + nj * 16 + lrow16) * LDS
                                                + ks * 16 + lhalf * 8) * 2);
                LDSM_X4(bfr[nj][0], bfr[nj][1], bfr[nj][2], bfr[nj][3], addr);
            }
#pragma unroll
            for (int mi = 0; mi < 4; mi++)
#pragma unroll
                for (int ni = 0; ni < 4; ni++) {
                    const int nj = ni >> 1, sub = ni & 1;
                    MMA_BF16(acc[mi][ni], af[mi], bfr[nj][sub], bfr[nj][sub + 2]);
                }
        }
        if (c + 1 < total) {
            __syncthreads();
            storeS((c + 1) & 1);
            __syncthreads();
        }
    }

    // epilogue: thread (lane) owns rows (lane>>2, +8), cols (lane&3)*2+{0,1}
    const int cr = lane >> 2;
    const int cc = (lane & 3) * 2;
#pragma unroll
    for (int mi = 0; mi < 4; mi++) {
#pragma unroll
        for (int ni = 0; ni < 4; ni++) {
            const int bn = wn + ni * 8 + cc;
            const int gn = n0 + bn;
            const long long r0 = m0 + wm + mi * 16 + cr;
            const long long r1 = r0 + 8;
            float v0 = acc[mi][ni][0] + bias_s[bn];
            float v1 = acc[mi][ni][1] + bias_s[bn + 1];
            float v2 = acc[mi][ni][2] + bias_s[bn];
            float v3 = acc[mi][ni][3] + bias_s[bn + 1];
            if (ACT == 1) { v0 = selu_f(v0); v1 = selu_f(v1); v2 = selu_f(v2); v3 = selu_f(v3); }
            if (SPLIT) {
                bf16 h0, l0, h1, l1;
                split2(v0, h0, l0); split2(v1, h1, l1);
                *(uint32_t*)(Chi + (long long)z * sC + r0 * ldc + gn) = pack_bf16(__bfloat162float(h0), __bfloat162float(h1));
                // pack directly from bf16 values:
                {
                    uint32_t hp = ((uint32_t)*(uint16_t*)&h1 << 16) | (uint32_t)*(uint16_t*)&h0;
                    uint32_t lp = ((uint32_t)*(uint16_t*)&l1 << 16) | (uint32_t)*(uint16_t*)&l0;
                    *(uint32_t*)(Chi + (long long)z * sC + r0 * ldc + gn) = hp;
                    *(uint32_t*)(Clo + (long long)z * sC + r0 * ldc + gn) = lp;
                }
                split2(v2, h0, l0); split2(v3, h1, l1);
                {
                    uint32_t hp = ((uint32_t)*(uint16_t*)&h1 << 16) | (uint32_t)*(uint16_t*)&h0;
                    uint32_t lp = ((uint32_t)*(uint16_t*)&l1 << 16) | (uint32_t)*(uint16_t*)&l0;
                    *(uint32_t*)(Chi + (long long)z * sC + r1 * ldc + gn) = hp;
                    *(uint32_t*)(Clo + (long long)z * sC + r1 * ldc + gn) = lp;
                }
            } else {
                *(float2*)(C + (long long)z * sC + r0 * ldc + gn) = make_float2(v0, v1);
                *(float2*)(C + (long long)z * sC + r1 * ldc + gn) = make_float2(v2, v3);
            }
        }
    }
}

// ---------------------------------------------------------------------------
// Elementwise kernels
// ---------------------------------------------------------------------------
__global__ void init_dft_split(bf16* __restrict__ Ch, bf16* __restrict__ Cl,
                               bf16* __restrict__ Sh, bf16* __restrict__ Sl,
                               int N, float signS)
{
    long long idx = (long long)blockIdx.x * blockDim.x + threadIdx.x;
    if (idx >= (long long)N * N) return;
    int i = (int)(idx / N), j = (int)(idx % N);
    int p = (int)(((long long)i * j) % N);
    float x = 2.0f * (float)p / (float)N;
    float s, c;
    sincospif(x, &s, &c);
    s *= signS;
    split2(c, Ch[idx], Cl[idx]);
    split2(s, Sh[idx], Sl[idx]);
}

__global__ void split_k(const float* __restrict__ in, bf16* __restrict__ h,
                        bf16* __restrict__ l, long long n)
{
    long long i = (long long)blockIdx.x * blockDim.x + threadIdx.x;
    if (i >= n) return;
    split2(in[i], h[i], l[i]);
}

// [R,C] fp32 -> [C,R] bf16 split, batched. grid (C/32, R/32, batch), block (32,8)
__global__ void split_trans(const float* __restrict__ in, bf16* __restrict__ oh,
                            bf16* __restrict__ ol, int R, int C,
                            long long sIn, long long sOut)
{
    __shared__ float t[32][33];
    const int z = blockIdx.z;
    const float* ib = in + (long long)z * sIn;
    const int c0 = blockIdx.x * 32, r0 = blockIdx.y * 32;
    const int tx = threadIdx.x, ty = threadIdx.y;
#pragma unroll
    for (int i = 0; i < 4; i++)
        t[ty + i * 8][tx] = ib[(long long)(r0 + ty + i * 8) * C + c0 + tx];
    __syncthreads();
#pragma unroll
    for (int i = 0; i < 4; i++) {
        float v = t[tx][ty + i * 8];
        long long o = (long long)z * sOut + (long long)(c0 + ty + i * 8) * R + r0 + tx;
        split2(v, oh[o], ol[o]);
    }
}

// softmax over H=4 heads (stride BSD), then split. layout unchanged.
__global__ void softmax_split(const float* __restrict__ q, bf16* __restrict__ oh,
                              bf16* __restrict__ ol)
{
    long long i = (long long)blockIdx.x * blockDim.x + threadIdx.x;
    if (i >= BSD) return;
    float v0 = q[i], v1 = q[i + BSD], v2 = q[i + 2 * BSD], v3 = q[i + 3 * BSD];
    float m = fmaxf(fmaxf(v0, v1), fmaxf(v2, v3));
    float e0 = expf(v0 - m), e1 = expf(v1 - m), e2 = expf(v2 - m), e3 = expf(v3 - m);
    float r = 1.f / (e0 + e1 + e2 + e3);
    split2(e0 * r, oh[i], ol[i]);
    split2(e1 * r, oh[i + BSD], ol[i + BSD]);
    split2(e2 * r, oh[i + 2 * BSD], ol[i + 2 * BSD]);
    split2(e3 * r, oh[i + 3 * BSD], ol[i + 3 * BSD]);
}

// softmax over heads + transpose: ks[h][b][s,d] -> ksT[z=h*B+b][d,s] split.
// grid (S/32, D/32, B), block (32,8)
__global__ void softmax_split_trans(const float* __restrict__ ks, bf16* __restrict__ oh,
                                    bf16* __restrict__ ol)
{
    __shared__ float t[4][32][33];
    const int b = blockIdx.z;
    const int s0 = blockIdx.x * 32, d0 = blockIdx.y * 32;
    const int tx = threadIdx.x, ty = threadIdx.y;
#pragma unroll
    for (int h = 0; h < 4; h++)
#pragma unroll
        for (int i = 0; i < 4; i++)
            t[h][ty + i * 8][tx] =
                ks[((long long)(h * Bm + b) * Sm + s0 + ty + i * 8) * Dm + d0 + tx];
    __syncthreads();
#pragma unroll
    for (int i = 0; i < 4; i++) {
        float v0 = t[0][ty + i * 8][tx], v1 = t[1][ty + i * 8][tx];
        float v2 = t[2][ty + i * 8][tx], v3 = t[3][ty + i * 8][tx];
        float m = fmaxf(fmaxf(v0, v1), fmaxf(v2, v3));
        float e0 = expf(v0 - m), e1 = expf(v1 - m), e2 = expf(v2 - m), e3 = expf(v3 - m);
        float r = 1.f / (e0 + e1 + e2 + e3);
        t[0][ty + i * 8][tx] = e0 * r; t[1][ty + i * 8][tx] = e1 * r;
        t[2][ty + i * 8][tx] = e2 * r; t[3][ty + i * 8][tx] = e3 * r;
    }
    __syncthreads();
#pragma unroll
    for (int h = 0; h < 4; h++)
#pragma unroll
        for (int i = 0; i < 4; i++) {
            float v = t[h][tx][ty + i * 8];
            long long o = (long long)(h * Bm + b) * SD + (long long)(d0 + ty + i * 8) * Sm + s0 + tx;
            split2(v, oh[o], ol[o]);
        }
}

// rearrange b h s d -> b s (d h), with split
__global__ void permute_split(const float* __restrict__ src, bf16* __restrict__ oh,
                              bf16* __restrict__ ol)
{
    long long o = (long long)blockIdx.x * blockDim.x + threadIdx.x;
    if (o >= BSD * Hn) return;
    int h = (int)(o & 3);
    long long r = o >> 2;
    int d = (int)(r & (Dm - 1));
    long long m = r >> 9;
    long long b = m >> 11;
    long long s = m & (Sm - 1);
    float v = src[(((long long)h * Bm + b) * Sm + s) * Dm + d];
    split2(v, oh[o], ol[o]);
}

// LN over last dim (D=512) of (a+b); optional split outputs.
__global__ void ln_split(const float* __restrict__ a, const float* __restrict__ bres,
                         const float* __restrict__ g, const float* __restrict__ be,
                         float* __restrict__ out, bf16* __restrict__ oh, bf16* __restrict__ ol)
{
    __shared__ float red[4];
    long long row = blockIdx.x;
    int t = threadIdx.x;  // 128
    float4 va = ((const float4*)(a + row * Dm))[t];
    float4 vb = ((const float4*)(bres + row * Dm))[t];
    float4 v = make_float4(va.x + vb.x, va.y + vb.y, va.z + vb.z, va.w + vb.w);
    float s = v.x + v.y + v.z + v.w;
#pragma unroll
    for (int o = 16; o > 0; o >>= 1) s += __shfl_xor_sync(0xffffffffu, s, o);
    if ((t & 31) == 0) red[t >> 5] = s;
    __syncthreads();
    float mu = (red[0] + red[1] + red[2] + red[3]) * (1.f / (float)Dm);
    __syncthreads();
    float d0 = v.x - mu, d1 = v.y - mu, d2 = v.z - mu, d3 = v.w - mu;
    float q = d0 * d0 + d1 * d1 + d2 * d2 + d3 * d3;
#pragma unroll
    for (int o = 16; o > 0; o >>= 1) q += __shfl_xor_sync(0xffffffffu, q, o);
    if ((t & 31) == 0) red[t >> 5] = q;
    __syncthreads();
    float var = (red[0] + red[1] + red[2] + red[3]) * (1.f / (float)Dm);
    float rstd = rsqrtf(var + 1e-5f);
    float4 vg = ((const float4*)g)[t];
    float4 vbe = ((const float4*)be)[t];
    float4 o4;
    o4.x = fmaf(vg.x, d0 * rstd, vbe.x);
    o4.y = fmaf(vg.y, d1 * rstd, vbe.y);
    o4.z = fmaf(vg.z, d2 * rstd, vbe.z);
    o4.w = fmaf(vg.w, d3 * rstd, vbe.w);
    ((float4*)(out + row * Dm))[t] = o4;
    if (oh) {
        long long o = row * Dm + t * 4;
        split2(o4.x, oh[o], ol[o]);
        split2(o4.y, oh[o + 1], ol[o + 1]);
        split2(o4.z, oh[o + 2], ol[o + 2]);
        split2(o4.w, oh[o + 3], ol[o + 3]);
    }
}

// ---------------------------------------------------------------------------
// Host
// ---------------------------------------------------------------------------
static TcPasses mk3(const bf16* Ah, const bf16* Al, const bf16* Bh, const bf16* Bl) {
    TcPasses P{};
    P.A[0] = Ah; P.B[0] = Bh;
    P.A[1] = Al; P.B[1] = Bh;
    P.A[2] = Ah; P.B[2] = Bl;
    return P;
}

static void tcg(const TcPasses& P, int np, float* C, bf16* Ch, bf16* Cl,
                int M, int N, int K, int lda, int ldb, int ldc,
                long long sA, long long sB, long long sC, int batch,
                const float* bias, int sBias, bool seluSplit)
{
    dim3 grid(N / 128, M / 128, batch), block(256);
    if (seluSplit)
        mma_gemm<1, 1><<<grid, block>>>(P, np, C, Ch, Cl, K, lda, ldb, ldc, sA, sB, sC, bias, sBias);
    else
        mma_gemm<0, 0><<<grid, block>>>(P, np, C, Ch, Cl, K, lda, ldb, ldc, sA, sB, sC, bias, sBias);
}

#define GETSYM(var, sym) do { void* _p; cudaGetSymbolAddress(&_p, sym); var = (decltype(var))_p; } while (0)

extern "C" void kernel_launch(void* const* d_in, const int* in_sizes, int n_in,
                              void* d_out, int out_size)
{
    const float* x_enc = (const float*)d_in[0];
    const float* x_dec = (const float*)d_in[1];
    const float* Wq = (const float*)d_in[2];
    const float* bq = (const float*)d_in[3];
    const float* Wk = (const float*)d_in[4];
    const float* bk = (const float*)d_in[5];
    const float* Wv = (const float*)d_in[6];
    const float* bv = (const float*)d_in[7];
    const float* Wo = (const float*)d_in[8];
    const float* bo = (const float*)d_in[9];
    const float* ln1g = (const float*)d_in[10];
    const float* ln1b = (const float*)d_in[11];
    const float* ln2g = (const float*)d_in[12];
    const float* ln2b = (const float*)d_in[13];
    const float* W1 = (const float*)d_in[14];
    const float* b1 = (const float*)d_in[15];
    const float* W2 = (const float*)d_in[16];
    const float* b2 = (const float*)d_in[17];
    const float* ln3g = (const float*)d_in[18];
    const float* ln3b = (const float*)d_in[19];
    float* outp = (float*)d_out;

    bf16 *CSh, *CSl, *SSh, *SSl, *BDh, *BDl;
    bf16 *xdh, *xdl, *xeh, *xel, *t12Th, *t12Tl, *xdsh, *xdsl;
    bf16 *qsh, *qsl, *ksTh, *ksTl, *vsTh, *vsTl, *gcTh, *gcTl, *oph, *opl;
    bf16 *WqTh, *WqTl, *WkTh, *WkTl, *WvTh, *WvTl, *WoTh, *WoTl, *W1Th, *W1Tl, *W2Th, *W2Tl;
    bf16 *x2h, *x2l, *midh, *midl;
    float *t12, *xf, *xd, *qs, *ks, *vs, *gc, *outb, *attn, *x2, *ff;
    GETSYM(CSh, g_CSh); GETSYM(CSl, g_CSl); GETSYM(SSh, g_SSh); GETSYM(SSl, g_SSl);
    GETSYM(BDh, g_BDh); GETSYM(BDl, g_BDl);
    GETSYM(xdh, g_xdh); GETSYM(xdl, g_xdl); GETSYM(xeh, g_xeh); GETSYM(xel, g_xel);
    GETSYM(t12, g_t12); GETSYM(t12Th, g_t12Th); GETSYM(t12Tl, g_t12Tl);
    GETSYM(xf, g_xf); GETSYM(xd, g_xd); GETSYM(xdsh, g_xdsh); GETSYM(xdsl, g_xdsl);
    GETSYM(qs, g_qs); GETSYM(ks, g_ks); GETSYM(vs, g_vs);
    GETSYM(qsh, g_qsh); GETSYM(qsl, g_qsl);
    GETSYM(ksTh, g_ksTh); GETSYM(ksTl, g_ksTl); GETSYM(vsTh, g_vsTh); GETSYM(vsTl, g_vsTl);
    GETSYM(gc, g_gc); GETSYM(gcTh, g_gcTh); GETSYM(gcTl, g_gcTl);
    GETSYM(outb, g_outb); GETSYM(oph, g_oph); GETSYM(opl, g_opl);
    GETSYM(WqTh, g_WqTh); GETSYM(WqTl, g_WqTl);
    GETSYM(WkTh, g_WkTh); GETSYM(WkTl, g_WkTl);
    GETSYM(WvTh, g_WvTh); GETSYM(WvTl, g_WvTl);
    GETSYM(WoTh, g_WoTh); GETSYM(WoTl, g_WoTl);
    GETSYM(W1Th, g_W1Th); GETSYM(W1Tl, g_W1Tl);
    GETSYM(W2Th, g_W2Th); GETSYM(W2Tl, g_W2Tl);
    GETSYM(attn, g_attn); GETSYM(x2, g_x2); GETSYM(x2h, g_x2h); GETSYM(x2l, g_x2l);
    GETSYM(midh, g_midh); GETSYM(midl, g_midl); GETSYM(ff, g_ff);

    dim3 tb(32, 8);

    // 0) DFT matrices (bf16 split; sin pre-negated for the S-side)
    init_dft_split<<<(Sm * Sm) / 256, 256>>>(CSh, CSl, SSh, SSl, Sm, -1.f);
    init_dft_split<<<(Dm * Dm) / 256, 256>>>(BDh, BDl, BDh + DD, BDl + DD, Dm, 1.f);

    // inputs split
    split_k<<<(int)(BSD / 256), 256>>>(x_dec, xdh, xdl, BSD);
    split_k<<<(int)(BSD / 256), 256>>>(x_enc, xeh, xel, BSD);

    // 1) t12 = x_dec @ [CD | SD]   (M=8192, N=1024, K=512)
    tcg(mk3(xdh, xdl, BDh, BDl), 3, t12, nullptr, nullptr,
        BSm, 1024, Dm, Dm, Dm, 1024, 0, 0, 0, 1, nullptr, 0, false);
    // transpose per batch: [2048,1024] -> [1024,2048]
    split_trans<<<dim3(1024 / 32, Sm / 32, Bm), tb>>>(t12, t12Th, t12Tl,
        Sm, 1024, (long long)Sm * 1024, (long long)1024 * Sm);

    // 2) xf = CS @ t1 - SS @ t2   (6-pass accumulation; M=2048,N=512,K=2048,z=4)
    {
        TcPasses P{};
        const bf16* t2h = t12Th + (long long)512 * Sm;
        const bf16* t2l = t12Tl + (long long)512 * Sm;
        P.A[0] = CSh; P.B[0] = t12Th;
        P.A[1] = CSl; P.B[1] = t12Th;
        P.A[2] = CSh; P.B[2] = t12Tl;
        P.A[3] = SSh; P.B[3] = t2h;
        P.A[4] = SSl; P.B[4] = t2h;
        P.A[5] = SSh; P.B[5] = t2l;
        tcg(P, 6, xf, nullptr, nullptr, Sm, Dm, Sm, Sm, Sm, Dm,
            0, (long long)1024 * Sm, SD, Bm, nullptr, 0, false);
    }

    // 3) xd = LN1(x_dec + xf), fused split
    ln_split<<<BSm, 128>>>(x_dec, xf, ln1g, ln1b, xd, xdsh, xdsl);

    // 4) weight transposes
    split_trans<<<dim3(16, 16, Hn), tb>>>(Wq, WqTh, WqTl, Dm, Dm, DD, DD);
    split_trans<<<dim3(16, 16, Hn), tb>>>(Wk, WkTh, WkTl, Dm, Dm, DD, DD);
    split_trans<<<dim3(16, 16, Hn), tb>>>(Wv, WvTh, WvTl, Dm, Dm, DD, DD);

    // 5) projections (z = head)
    tcg(mk3(xdsh, xdsl, WqTh, WqTl), 3, qs, nullptr, nullptr,
        BSm, Dm, Dm, Dm, Dm, Dm, 0, DD, BSD, Hn, bq, Dm, false);
    tcg(mk3(xeh, xel, WkTh, WkTl), 3, ks, nullptr, nullptr,
        BSm, Dm, Dm, Dm, Dm, Dm, 0, DD, BSD, Hn, bk, Dm, false);
    tcg(mk3(xeh, xel, WvTh, WvTl), 3, vs, nullptr, nullptr,
        BSm, Dm, Dm, Dm, Dm, Dm, 0, DD, BSD, Hn, bv, Dm, false);

    // 6) softmax over heads (+ split, + transpose for k), vs transpose
    softmax_split<<<(int)(BSD / 256), 256>>>(qs, qsh, qsl);
    softmax_split_trans<<<dim3(Sm / 32, Dm / 32, Bm), tb>>>(ks, ksTh, ksTl);
    split_trans<<<dim3(Dm / 32, Sm / 32, 16), tb>>>(vs, vsTh, vsTl, Sm, Dm, SD, SD);

    // 7) gc[z] = ksT @ vsT^T  (M=512,N=512,K=2048,z=16)
    tcg(mk3(ksTh, ksTl, vsTh, vsTl), 3, gc, nullptr, nullptr,
        Dm, Dm, Sm, Sm, Sm, Dm, SD, SD, DD, 16, nullptr, 0, false);
    split_trans<<<dim3(16, 16, 16), tb>>>(gc, gcTh, gcTl, Dm, Dm, DD, DD);

    // 8) out[z] = qs @ gc  (M=2048,N=512,K=512,z=16)
    tcg(mk3(qsh, qsl, gcTh, gcTl), 3, outb, nullptr, nullptr,
        Sm, Dm, Dm, Dm, Dm, Dm, SD, DD, SD, 16, nullptr, 0, false);

    // 9) rearrange + split
    permute_split<<<(int)((BSD * Hn) / 256), 256>>>(outb, oph, opl);

    // 10) attn = operm @ Wo + bo  (M=8192,N=512,K=2048)
    split_trans<<<dim3(Dm / 32, 2048 / 32, 1), tb>>>(Wo, WoTh, WoTl, 2048, Dm, 0, 0);
    tcg(mk3(oph, opl, WoTh, WoTl), 3, attn, nullptr, nullptr,
        BSm, Dm, 2048, 2048, 2048, Dm, 0, 0, 0, 1, bo, 0, false);

    // 11) x2 = LN2(xd + attn), fused split
    ln_split<<<BSm, 128>>>(xd, attn, ln2g, ln2b, x2, x2h, x2l);

    // 12) mid = selu(x2 @ W1 + b1), epilogue writes bf16 split directly
    split_trans<<<dim3(MIDm / 32, Dm / 32, 1), tb>>>(W1, W1Th, W1Tl, Dm, MIDm, 0, 0);
    tcg(mk3(x2h, x2l, W1Th, W1Tl), 3, nullptr, midh, midl,
        BSm, MIDm, Dm, Dm, Dm, MIDm, 0, 0, 0, 1, b1, 0, true);

    // 13) ff = mid @ W2 + b2  (M=8192,N=512,K=2048)
    split_trans<<<dim3(Dm / 32, MIDm / 32, 1), tb>>>(W2, W2Th, W2Tl, MIDm, Dm, 0, 0);
    tcg(mk3(midh, midl, W2Th, W2Tl), 3, ff, nullptr, nullptr,
        BSm, Dm, MIDm, MIDm, MIDm, Dm, 0, 0, 0, 1, b2, 0, false);

    // 14) out = LN3(x2 + ff)
    ln_split<<<BSm, 128>>>(x2, ff, ln3g, ln3b, outp, nullptr, nullptr);
}

// round 4
// speedup vs baseline: 2.0470x; 1.3332x over previous
#include <cuda_runtime.h>
#include <cuda_bf16.h>
#include <math.h>
#include <stdint.h>

typedef __nv_bfloat16 bf16;

static constexpr int Dm = 512, Hn = 4, MIDm = 2048, Bm = 4, Sm = 2048;
static constexpr int BSm = Bm * Sm;                      // 8192
static constexpr long long BSD = (long long)BSm * Dm;    // 4194304
static constexpr long long SD  = (long long)Sm * Dm;     // 1048576
static constexpr long long DD  = (long long)Dm * Dm;     // 262144

// ---------------------------------------------------------------------------
// Static device scratch (no allocations anywhere). 256B-aligned for cp.async.
// ---------------------------------------------------------------------------
__device__ __align__(256) bf16 g_CSh[4194304], g_CSl[4194304];
__device__ __align__(256) bf16 g_SSh[4194304], g_SSl[4194304];   // NEGATED sin
__device__ __align__(256) bf16 g_BDh[524288],  g_BDl[524288];    // [CD ; SD] [1024,512]
__device__ __align__(256) bf16 g_xdh[4194304], g_xdl[4194304];
__device__ __align__(256) bf16 g_xeh[4194304], g_xel[4194304];
__device__ __align__(256) float g_t12[8388608];                  // [8192,1024]
__device__ __align__(256) bf16 g_t12Th[8388608], g_t12Tl[8388608]; // [4][1024,2048]
__device__ __align__(256) float g_xf[4194304];
__device__ __align__(256) float g_xd[4194304];
__device__ __align__(256) bf16 g_xdsh[4194304], g_xdsl[4194304];
__device__ __align__(256) float g_qs[16777216], g_ks[16777216], g_vs[16777216];
__device__ __align__(256) bf16 g_qsh[16777216], g_qsl[16777216];
__device__ __align__(256) bf16 g_ksTh[16777216], g_ksTl[16777216]; // [z][D,S]
__device__ __align__(256) bf16 g_vsTh[16777216], g_vsTl[16777216]; // [z][D,S]
__device__ __align__(256) float g_gc[4194304];                   // [16][512,512]
__device__ __align__(256) bf16 g_gcTh[4194304], g_gcTl[4194304];
__device__ __align__(256) float g_outb[16777216];                // [z][s,d]
__device__ __align__(256) bf16 g_oph[16777216], g_opl[16777216]; // [8192,2048]
__device__ __align__(256) bf16 g_WqTh[1048576], g_WqTl[1048576];
__device__ __align__(256) bf16 g_WkTh[1048576], g_WkTl[1048576];
__device__ __align__(256) bf16 g_WvTh[1048576], g_WvTl[1048576];
__device__ __align__(256) bf16 g_WoTh[1048576], g_WoTl[1048576]; // [512,2048]
__device__ __align__(256) bf16 g_W1Th[1048576], g_W1Tl[1048576]; // [2048,512]
__device__ __align__(256) bf16 g_W2Th[1048576], g_W2Tl[1048576]; // [512,2048]
__device__ __align__(256) float g_attn[4194304];
__device__ __align__(256) float g_x2[4194304];
__device__ __align__(256) bf16 g_x2h[4194304], g_x2l[4194304];
__device__ __align__(256) bf16 g_midh[16777216], g_midl[16777216];
__device__ __align__(256) float g_ff[4194304];

// ---------------------------------------------------------------------------
// Helpers
// ---------------------------------------------------------------------------
__device__ __forceinline__ uint32_t smem_u32(const void* p) {
    uint32_t a;
    asm("{ .reg .u64 t; cvta.to.shared.u64 t, %1; cvt.u32.u64 %0, t; }" : "=r"(a) : "l"(p));
    return a;
}
__device__ __forceinline__ float selu_f(float x) {
    const float sc = 1.0507009873554805f, al = 1.6732632423543772f;
    return x > 0.f ? sc * x : sc * al * (expf(x) - 1.f);
}
__device__ __forceinline__ void split2(float x, bf16& h, bf16& l) {
    h = __float2bfloat16(x);
    l = __float2bfloat16(x - __bfloat162float(h));
}

#define LDSM_X4(r0, r1, r2, r3, addr) \
    asm volatile("ldmatrix.sync.aligned.m8n8.x4.shared.b16 {%0,%1,%2,%3}, [%4];" \
        : "=r"(r0), "=r"(r1), "=r"(r2), "=r"(r3) : "r"(addr))

#define MMA_BF16(d, a, b0, b1) \
    asm volatile("mma.sync.aligned.m16n8k16.row.col.f32.bf16.bf16.f32 " \
        "{%0,%1,%2,%3}, {%4,%5,%6,%7}, {%8,%9}, {%0,%1,%2,%3};" \
        : "+f"((d)[0]), "+f"((d)[1]), "+f"((d)[2]), "+f"((d)[3]) \
        : "r"((a)[0]), "r"((a)[1]), "r"((a)[2]), "r"((a)[3]), "r"(b0), "r"(b1))

#define CP_ASYNC16(dst, src) \
    asm volatile("cp.async.cg.shared.global [%0], [%1], 16;" :: "r"(dst), "l"(src))
#define CP_COMMIT() asm volatile("cp.async.commit_group;")
#define CP_WAIT1()  asm volatile("cp.async.wait_group 1;")

// ---------------------------------------------------------------------------
// HMMA GEMM with cp.async 3-stage pipeline.
// C[z] = sum_p A_p[z] @ B_p[z]^T (+bias)(+SELU)(fp32 or bf16-split out)
// A_p: [M,K] bf16 row-major; B_p: [N,K] bf16 row-major (B^T layout).
// Block 128x128, 8 warps (2x4), warp tile 64x32, mma.m16n8k16, BK=64.
// M,N % 128 == 0; K % 64 == 0.
// ---------------------------------------------------------------------------
struct TcPasses { const bf16* A[6]; const bf16* B[6]; };

static constexpr int BKg = 64;
static constexpr int LDSg = BKg + 8;                 // 72 elems (144B rows)
static constexpr int TILE_B = 128 * LDSg * 2;        // 18432 bytes per tile
static constexpr int STAGES = 3;
static constexpr int SMEM_A_OFF = 0;
static constexpr int SMEM_B_OFF = STAGES * TILE_B;   // 55296
static constexpr int SMEM_BIAS_OFF = 2 * STAGES * TILE_B;  // 110592
static constexpr int SMEM_G = SMEM_BIAS_OFF + 128 * 4;     // 111104

template <int ACT, int SPLIT>
__global__ __launch_bounds__(256, 2) void mma_gemm(
    TcPasses P, int npass,
    float* __restrict__ C, bf16* __restrict__ Chi, bf16* __restrict__ Clo,
    int K, int lda, int ldb, int ldc,
    long long sA, long long sB, long long sC,
    const float* __restrict__ bias, int sBias)
{
    extern __shared__ char smem[];
    float* bias_s = (float*)(smem + SMEM_BIAS_OFF);
    const uint32_t sA0 = smem_u32(smem) + SMEM_A_OFF;
    const uint32_t sB0 = smem_u32(smem) + SMEM_B_OFF;

    const int tid = threadIdx.x;
    const int lane = tid & 31;
    const int wid = tid >> 5;
    const int wm = (wid & 1) * 64;
    const int wn = (wid >> 1) * 32;
    const int z = blockIdx.z;
    const int m0 = blockIdx.y * 128, n0 = blockIdx.x * 128;

    if (tid < 128) bias_s[tid] = bias ? bias[(long long)z * sBias + n0 + tid] : 0.f;

    float acc[4][4][4];
#pragma unroll
    for (int i = 0; i < 4; i++)
#pragma unroll
        for (int j = 0; j < 4; j++)
#pragma unroll
            for (int k = 0; k < 4; k++) acc[i][j][k] = 0.f;

    const int cpp = K / BKg;
    const int total = npass * cpp;

    // copy mapping: chunk q = i*256+tid; row=q>>3 (0..127), col16=q&7 (8 elems)
    const int crow = tid >> 3;
    const int ccol = (tid & 7) * 8;

    auto loadStage = [&](int c, int stg) {
        int p = c / cpp;
        int k0 = (c - p * cpp) * BKg;
        const bf16* Ab = P.A[p] + (long long)z * sA + k0 + ccol;
        const bf16* Bb = P.B[p] + (long long)z * sB + k0 + ccol;
        uint32_t da = sA0 + stg * TILE_B + (crow * LDSg + ccol) * 2;
        uint32_t db = sB0 + stg * TILE_B + (crow * LDSg + ccol) * 2;
#pragma unroll
        for (int i = 0; i < 4; i++) {
            int row = crow + i * 32;
            CP_ASYNC16(da + i * 32 * LDSg * 2, Ab + (long long)(m0 + row) * lda);
            CP_ASYNC16(db + i * 32 * LDSg * 2, Bb + (long long)(n0 + row) * ldb);
        }
    };

    // prologue: stages 0,1
    loadStage(0, 0); CP_COMMIT();
    loadStage(1, 1); CP_COMMIT();

    const int lrow16 = lane & 15;
    const int lhalf = lane >> 4;

    for (int c = 0; c < total; c++) {
        CP_WAIT1();
        __syncthreads();
        const int stg = c % STAGES;
        const uint32_t aB = sA0 + stg * TILE_B;
        const uint32_t bB = sB0 + stg * TILE_B;
#pragma unroll
        for (int ks = 0; ks < 4; ks++) {
            uint32_t af[4][4];
#pragma unroll
            for (int mi = 0; mi < 4; mi++) {
                uint32_t addr = aB + (uint32_t)(((wm + mi * 16 + lrow16) * LDSg
                                                + ks * 16 + lhalf * 8) * 2);
                LDSM_X4(af[mi][0], af[mi][1], af[mi][2], af[mi][3], addr);
            }
            uint32_t bfr[2][4];
#pragma unroll
            for (int nj = 0; nj < 2; nj++) {
                uint32_t addr = bB + (uint32_t)(((wn + nj * 16 + lrow16) * LDSg
                                                + ks * 16 + lhalf * 8) * 2);
                LDSM_X4(bfr[nj][0], bfr[nj][1], bfr[nj][2], bfr[nj][3], addr);
            }
#pragma unroll
            for (int mi = 0; mi < 4; mi++)
#pragma unroll
                for (int ni = 0; ni < 4; ni++) {
                    const int nj = ni >> 1, sub = ni & 1;
                    MMA_BF16(acc[mi][ni], af[mi], bfr[nj][sub], bfr[nj][sub + 2]);
                }
        }
        if (c + 2 < total) loadStage(c + 2, (c + 2) % STAGES);
        CP_COMMIT();
    }

    // epilogue: lane owns rows (lane>>2, +8), cols (lane&3)*2+{0,1}
    const int cr = lane >> 2;
    const int cc = (lane & 3) * 2;
#pragma unroll
    for (int mi = 0; mi < 4; mi++) {
#pragma unroll
        for (int ni = 0; ni < 4; ni++) {
            const int bn = wn + ni * 8 + cc;
            const int gn = n0 + bn;
            const long long r0 = m0 + wm + mi * 16 + cr;
            const long long r1 = r0 + 8;
            float v0 = acc[mi][ni][0] + bias_s[bn];
            float v1 = acc[mi][ni][1] + bias_s[bn + 1];
            float v2 = acc[mi][ni][2] + bias_s[bn];
            float v3 = acc[mi][ni][3] + bias_s[bn + 1];
            if (ACT == 1) { v0 = selu_f(v0); v1 = selu_f(v1); v2 = selu_f(v2); v3 = selu_f(v3); }
            if (SPLIT) {
                bf16 h0, l0, h1, l1;
                split2(v0, h0, l0); split2(v1, h1, l1);
                uint32_t hp = ((uint32_t)*(uint16_t*)&h1 << 16) | (uint32_t)*(uint16_t*)&h0;
                uint32_t lp = ((uint32_t)*(uint16_t*)&l1 << 16) | (uint32_t)*(uint16_t*)&l0;
                *(uint32_t*)(Chi + (long long)z * sC + r0 * ldc + gn) = hp;
                *(uint32_t*)(Clo + (long long)z * sC + r0 * ldc + gn) = lp;
                split2(v2, h0, l0); split2(v3, h1, l1);
                hp = ((uint32_t)*(uint16_t*)&h1 << 16) | (uint32_t)*(uint16_t*)&h0;
                lp = ((uint32_t)*(uint16_t*)&l1 << 16) | (uint32_t)*(uint16_t*)&l0;
                *(uint32_t*)(Chi + (long long)z * sC + r1 * ldc + gn) = hp;
                *(uint32_t*)(Clo + (long long)z * sC + r1 * ldc + gn) = lp;
            } else {
                *(float2*)(C + (long long)z * sC + r0 * ldc + gn) = make_float2(v0, v1);
                *(float2*)(C + (long long)z * sC + r1 * ldc + gn) = make_float2(v2, v3);
            }
        }
    }
}

// ---------------------------------------------------------------------------
// Elementwise kernels
// ---------------------------------------------------------------------------
__global__ void init_dft_split(bf16* __restrict__ Ch, bf16* __restrict__ Cl,
                               bf16* __restrict__ Sh, bf16* __restrict__ Sl,
                               int N, float signS)
{
    long long idx = (long long)blockIdx.x * blockDim.x + threadIdx.x;
    if (idx >= (long long)N * N) return;
    int i = (int)(idx / N), j = (int)(idx % N);
    int p = (int)(((long long)i * j) % N);
    float x = 2.0f * (float)p / (float)N;
    float s, c;
    sincospif(x, &s, &c);
    s *= signS;
    split2(c, Ch[idx], Cl[idx]);
    split2(s, Sh[idx], Sl[idx]);
}

__global__ void split_k(const float* __restrict__ in, bf16* __restrict__ h,
                        bf16* __restrict__ l, long long n)
{
    long long i = (long long)blockIdx.x * blockDim.x + threadIdx.x;
    if (i >= n) return;
    split2(in[i], h[i], l[i]);
}

// [R,C] fp32 -> [C,R] bf16 split, batched. grid (C/32, R/32, batch), block (32,8)
__global__ void split_trans(const float* __restrict__ in, bf16* __restrict__ oh,
                            bf16* __restrict__ ol, int R, int C,
                            long long sIn, long long sOut)
{
    __shared__ float t[32][33];
    const int z = blockIdx.z;
    const float* ib = in + (long long)z * sIn;
    const int c0 = blockIdx.x * 32, r0 = blockIdx.y * 32;
    const int tx = threadIdx.x, ty = threadIdx.y;
#pragma unroll
    for (int i = 0; i < 4; i++)
        t[ty + i * 8][tx] = ib[(long long)(r0 + ty + i * 8) * C + c0 + tx];
    __syncthreads();
#pragma unroll
    for (int i = 0; i < 4; i++) {
        float v = t[tx][ty + i * 8];
        long long o = (long long)z * sOut + (long long)(c0 + ty + i * 8) * R + r0 + tx;
        split2(v, oh[o], ol[o]);
    }
}

// softmax over H=4 heads (stride BSD), then split.
__global__ void softmax_split(const float* __restrict__ q, bf16* __restrict__ oh,
                              bf16* __restrict__ ol)
{
    long long i = (long long)blockIdx.x * blockDim.x + threadIdx.x;
    if (i >= BSD) return;
    float v0 = q[i], v1 = q[i + BSD], v2 = q[i + 2 * BSD], v3 = q[i + 3 * BSD];
    float m = fmaxf(fmaxf(v0, v1), fmaxf(v2, v3));
    float e0 = expf(v0 - m), e1 = expf(v1 - m), e2 = expf(v2 - m), e3 = expf(v3 - m);
    float r = 1.f / (e0 + e1 + e2 + e3);
    split2(e0 * r, oh[i], ol[i]);
    split2(e1 * r, oh[i + BSD], ol[i + BSD]);
    split2(e2 * r, oh[i + 2 * BSD], ol[i + 2 * BSD]);
    split2(e3 * r, oh[i + 3 * BSD], ol[i + 3 * BSD]);
}

// softmax over heads + transpose: ks[h][b][s,d] -> ksT[z=h*B+b][d,s] split.
__global__ void softmax_split_trans(const float* __restrict__ ks, bf16* __restrict__ oh,
                                    bf16* __restrict__ ol)
{
    __shared__ float t[4][32][33];
    const int b = blockIdx.z;
    const int s0 = blockIdx.x * 32, d0 = blockIdx.y * 32;
    const int tx = threadIdx.x, ty = threadIdx.y;
#pragma unroll
    for (int h = 0; h < 4; h++)
#pragma unroll
        for (int i = 0; i < 4; i++)
            t[h][ty + i * 8][tx] =
                ks[((long long)(h * Bm + b) * Sm + s0 + ty + i * 8) * Dm + d0 + tx];
    __syncthreads();
#pragma unroll
    for (int i = 0; i < 4; i++) {
        float v0 = t[0][ty + i * 8][tx], v1 = t[1][ty + i * 8][tx];
        float v2 = t[2][ty + i * 8][tx], v3 = t[3][ty + i * 8][tx];
        float m = fmaxf(fmaxf(v0, v1), fmaxf(v2, v3));
        float e0 = expf(v0 - m), e1 = expf(v1 - m), e2 = expf(v2 - m), e3 = expf(v3 - m);
        float r = 1.f / (e0 + e1 + e2 + e3);
        t[0][ty + i * 8][tx] = e0 * r; t[1][ty + i * 8][tx] = e1 * r;
        t[2][ty + i * 8][tx] = e2 * r; t[3][ty + i * 8][tx] = e3 * r;
    }
    __syncthreads();
#pragma unroll
    for (int h = 0; h < 4; h++)
#pragma unroll
        for (int i = 0; i < 4; i++) {
            float v = t[h][tx][ty + i * 8];
            long long o = (long long)(h * Bm + b) * SD + (long long)(d0 + ty + i * 8) * Sm + s0 + tx;
            split2(v, oh[o], ol[o]);
        }
}

// rearrange b h s d -> b s (d h), with split
__global__ void permute_split(const float* __restrict__ src, bf16* __restrict__ oh,
                              bf16* __restrict__ ol)
{
    long long o = (long long)blockIdx.x * blockDim.x + threadIdx.x;
    if (o >= BSD * Hn) return;
    int h = (int)(o & 3);
    long long r = o >> 2;
    int d = (int)(r & (Dm - 1));
    long long m = r >> 9;
    long long b = m >> 11;
    long long s = m & (Sm - 1);
    float v = src[(((long long)h * Bm + b) * Sm + s) * Dm + d];
    split2(v, oh[o], ol[o]);
}

// LN over last dim (D=512) of (a+b); optional split outputs.
__global__ void ln_split(const float* __restrict__ a, const float* __restrict__ bres,
                         const float* __restrict__ g, const float* __restrict__ be,
                         float* __restrict__ out, bf16* __restrict__ oh, bf16* __restrict__ ol)
{
    __shared__ float red[4];
    long long row = blockIdx.x;
    int t = threadIdx.x;  // 128
    float4 va = ((const float4*)(a + row * Dm))[t];
    float4 vb = ((const float4*)(bres + row * Dm))[t];
    float4 v = make_float4(va.x + vb.x, va.y + vb.y, va.z + vb.z, va.w + vb.w);
    float s = v.x + v.y + v.z + v.w;
#pragma unroll
    for (int o = 16; o > 0; o >>= 1) s += __shfl_xor_sync(0xffffffffu, s, o);
    if ((t & 31) == 0) red[t >> 5] = s;
    __syncthreads();
    float mu = (red[0] + red[1] + red[2] + red[3]) * (1.f / (float)Dm);
    __syncthreads();
    float d0 = v.x - mu, d1 = v.y - mu, d2 = v.z - mu, d3 = v.w - mu;
    float q = d0 * d0 + d1 * d1 + d2 * d2 + d3 * d3;
#pragma unroll
    for (int o = 16; o > 0; o >>= 1) q += __shfl_xor_sync(0xffffffffu, q, o);
    if ((t & 31) == 0) red[t >> 5] = q;
    __syncthreads();
    float var = (red[0] + red[1] + red[2] + red[3]) * (1.f / (float)Dm);
    float rstd = rsqrtf(var + 1e-5f);
    float4 vg = ((const float4*)g)[t];
    float4 vbe = ((const float4*)be)[t];
    float4 o4;
    o4.x = fmaf(vg.x, d0 * rstd, vbe.x);
    o4.y = fmaf(vg.y, d1 * rstd, vbe.y);
    o4.z = fmaf(vg.z, d2 * rstd, vbe.z);
    o4.w = fmaf(vg.w, d3 * rstd, vbe.w);
    ((float4*)(out + row * Dm))[t] = o4;
    if (oh) {
        long long o = row * Dm + t * 4;
        split2(o4.x, oh[o], ol[o]);
        split2(o4.y, oh[o + 1], ol[o + 1]);
        split2(o4.z, oh[o + 2], ol[o + 2]);
        split2(o4.w, oh[o + 3], ol[o + 3]);
    }
}

// ---------------------------------------------------------------------------
// Host
// ---------------------------------------------------------------------------
static TcPasses mk3(const bf16* Ah, const bf16* Al, const bf16* Bh, const bf16* Bl) {
    TcPasses P{};
    P.A[0] = Ah; P.B[0] = Bh;
    P.A[1] = Al; P.B[1] = Bh;
    P.A[2] = Ah; P.B[2] = Bl;
    return P;
}

static void tcg(const TcPasses& P, int np, float* C, bf16* Ch, bf16* Cl,
                int M, int N, int K, int lda, int ldb, int ldc,
                long long sA, long long sB, long long sC, int batch,
                const float* bias, int sBias, bool seluSplit)
{
    dim3 grid(N / 128, M / 128, batch), block(256);
    if (seluSplit)
        mma_gemm<1, 1><<<grid, block, SMEM_G>>>(P, np, C, Ch, Cl, K, lda, ldb, ldc, sA, sB, sC, bias, sBias);
    else
        mma_gemm<0, 0><<<grid, block, SMEM_G>>>(P, np, C, Ch, Cl, K, lda, ldb, ldc, sA, sB, sC, bias, sBias);
}

#define GETSYM(var, sym) do { void* _p; cudaGetSymbolAddress(&_p, sym); var = (decltype(var))_p; } while (0)

extern "C" void kernel_launch(void* const* d_in, const int* in_sizes, int n_in,
                              void* d_out, int out_size)
{
    const float* x_enc = (const float*)d_in[0];
    const float* x_dec = (const float*)d_in[1];
    const float* Wq = (const float*)d_in[2];
    const float* bq = (const float*)d_in[3];
    const float* Wk = (const float*)d_in[4];
    const float* bk = (const float*)d_in[5];
    const float* Wv = (const float*)d_in[6];
    const float* bv = (const float*)d_in[7];
    const float* Wo = (const float*)d_in[8];
    const float* bo = (const float*)d_in[9];
    const float* ln1g = (const float*)d_in[10];
    const float* ln1b = (const float*)d_in[11];
    const float* ln2g = (const float*)d_in[12];
    const float* ln2b = (const float*)d_in[13];
    const float* W1 = (const float*)d_in[14];
    const float* b1 = (const float*)d_in[15];
    const float* W2 = (const float*)d_in[16];
    const float* b2 = (const float*)d_in[17];
    const float* ln3g = (const float*)d_in[18];
    const float* ln3b = (const float*)d_in[19];
    float* outp = (float*)d_out;

    bf16 *CSh, *CSl, *SSh, *SSl, *BDh, *BDl;
    bf16 *xdh, *xdl, *xeh, *xel, *t12Th, *t12Tl, *xdsh, *xdsl;
    bf16 *qsh, *qsl, *ksTh, *ksTl, *vsTh, *vsTl, *gcTh, *gcTl, *oph, *opl;
    bf16 *WqTh, *WqTl, *WkTh, *WkTl, *WvTh, *WvTl, *WoTh, *WoTl, *W1Th, *W1Tl, *W2Th, *W2Tl;
    bf16 *x2h, *x2l, *midh, *midl;
    float *t12, *xf, *xd, *qs, *ks, *vs, *gc, *outb, *attn, *x2, *ff;
    GETSYM(CSh, g_CSh); GETSYM(CSl, g_CSl); GETSYM(SSh, g_SSh); GETSYM(SSl, g_SSl);
    GETSYM(BDh, g_BDh); GETSYM(BDl, g_BDl);
    GETSYM(xdh, g_xdh); GETSYM(xdl, g_xdl); GETSYM(xeh, g_xeh); GETSYM(xel, g_xel);
    GETSYM(t12, g_t12); GETSYM(t12Th, g_t12Th); GETSYM(t12Tl, g_t12Tl);
    GETSYM(xf, g_xf); GETSYM(xd, g_xd); GETSYM(xdsh, g_xdsh); GETSYM(xdsl, g_xdsl);
    GETSYM(qs, g_qs); GETSYM(ks, g_ks); GETSYM(vs, g_vs);
    GETSYM(qsh, g_qsh); GETSYM(qsl, g_qsl);
    GETSYM(ksTh, g_ksTh); GETSYM(ksTl, g_ksTl); GETSYM(vsTh, g_vsTh); GETSYM(vsTl, g_vsTl);
    GETSYM(gc, g_gc); GETSYM(gcTh, g_gcTh); GETSYM(gcTl, g_gcTl);
    GETSYM(outb, g_outb); GETSYM(oph, g_oph); GETSYM(opl, g_opl);
    GETSYM(WqTh, g_WqTh); GETSYM(WqTl, g_WqTl);
    GETSYM(WkTh, g_WkTh); GETSYM(WkTl, g_WkTl);
    GETSYM(WvTh, g_WvTh); GETSYM(WvTl, g_WvTl);
    GETSYM(WoTh, g_WoTh); GETSYM(WoTl, g_WoTl);
    GETSYM(W1Th, g_W1Th); GETSYM(W1Tl, g_W1Tl);
    GETSYM(W2Th, g_W2Th); GETSYM(W2Tl, g_W2Tl);
    GETSYM(attn, g_attn); GETSYM(x2, g_x2); GETSYM(x2h, g_x2h); GETSYM(x2l, g_x2l);
    GETSYM(midh, g_midh); GETSYM(midl, g_midl); GETSYM(ff, g_ff);

    cudaFuncSetAttribute(mma_gemm<0, 0>, cudaFuncAttributeMaxDynamicSharedMemorySize, SMEM_G);
    cudaFuncSetAttribute(mma_gemm<1, 1>, cudaFuncAttributeMaxDynamicSharedMemorySize, SMEM_G);

    dim3 tb(32, 8);

    // 0) DFT matrices (bf16 split; sin pre-negated for the S-side)
    init_dft_split<<<(Sm * Sm) / 256, 256>>>(CSh, CSl, SSh, SSl, Sm, -1.f);
    init_dft_split<<<(Dm * Dm) / 256, 256>>>(BDh, BDl, BDh + DD, BDl + DD, Dm, 1.f);

    // inputs split
    split_k<<<(int)(BSD / 256), 256>>>(x_dec, xdh, xdl, BSD);
    split_k<<<(int)(BSD / 256), 256>>>(x_enc, xeh, xel, BSD);

    // 1) t12 = x_dec @ [CD | SD]   (M=8192, N=1024, K=512)
    tcg(mk3(xdh, xdl, BDh, BDl), 3, t12, nullptr, nullptr,
        BSm, 1024, Dm, Dm, Dm, 1024, 0, 0, 0, 1, nullptr, 0, false);
    // transpose per batch: [2048,1024] -> [1024,2048]
    split_trans<<<dim3(1024 / 32, Sm / 32, Bm), tb>>>(t12, t12Th, t12Tl,
        Sm, 1024, (long long)Sm * 1024, (long long)1024 * Sm);

    // 2) xf = CS @ t1 - SS @ t2   (6-pass accumulation; M=2048,N=512,K=2048,z=4)
    {
        TcPasses P{};
        const bf16* t2h = t12Th + (long long)512 * Sm;
        const bf16* t2l = t12Tl + (long long)512 * Sm;
        P.A[0] = CSh; P.B[0] = t12Th;
        P.A[1] = CSl; P.B[1] = t12Th;
        P.A[2] = CSh; P.B[2] = t12Tl;
        P.A[3] = SSh; P.B[3] = t2h;
        P.A[4] = SSl; P.B[4] = t2h;
        P.A[5] = SSh; P.B[5] = t2l;
        tcg(P, 6, xf, nullptr, nullptr, Sm, Dm, Sm, Sm, Sm, Dm,
            0, (long long)1024 * Sm, SD, Bm, nullptr, 0, false);
    }

    // 3) xd = LN1(x_dec + xf), fused split
    ln_split<<<BSm, 128>>>(x_dec, xf, ln1g, ln1b, xd, xdsh, xdsl);

    // 4) weight transposes
    split_trans<<<dim3(16, 16, Hn), tb>>>(Wq, WqTh, WqTl, Dm, Dm, DD, DD);
    split_trans<<<dim3(16, 16, Hn), tb>>>(Wk, WkTh, WkTl, Dm, Dm, DD, DD);
    split_trans<<<dim3(16, 16, Hn), tb>>>(Wv, WvTh, WvTl, Dm, Dm, DD, DD);

    // 5) projections (z = head)
    tcg(mk3(xdsh, xdsl, WqTh, WqTl), 3, qs, nullptr, nullptr,
        BSm, Dm, Dm, Dm, Dm, Dm, 0, DD, BSD, Hn, bq, Dm, false);
    tcg(mk3(xeh, xel, WkTh, WkTl), 3, ks, nullptr, nullptr,
        BSm, Dm, Dm, Dm, Dm, Dm, 0, DD, BSD, Hn, bk, Dm, false);
    tcg(mk3(xeh, xel, WvTh, WvTl), 3, vs, nullptr, nullptr,
        BSm, Dm, Dm, Dm, Dm, Dm, 0, DD, BSD, Hn, bv, Dm, false);

    // 6) softmax over heads (+ split, + transpose for k), vs transpose
    softmax_split<<<(int)(BSD / 256), 256>>>(qs, qsh, qsl);
    softmax_split_trans<<<dim3(Sm / 32, Dm / 32, Bm), tb>>>(ks, ksTh, ksTl);
    split_trans<<<dim3(Dm / 32, Sm / 32, 16), tb>>>(vs, vsTh, vsTl, Sm, Dm, SD, SD);

    // 7) gc[z] = ksT @ vsT^T  (M=512,N=512,K=2048,z=16)
    tcg(mk3(ksTh, ksTl, vsTh, vsTl), 3, gc, nullptr, nullptr,
        Dm, Dm, Sm, Sm, Sm, Dm, SD, SD, DD, 16, nullptr, 0, false);
    split_trans<<<dim3(16, 16, 16), tb>>>(gc, gcTh, gcTl, Dm, Dm, DD, DD);

    // 8) out[z] = qs @ gc  (M=2048,N=512,K=512,z=16)
    tcg(mk3(qsh, qsl, gcTh, gcTl), 3, outb, nullptr, nullptr,
        Sm, Dm, Dm, Dm, Dm, Dm, SD, DD, SD, 16, nullptr, 0, false);

    // 9) rearrange + split
    permute_split<<<(int)((BSD * Hn) / 256), 256>>>(outb, oph, opl);

    // 10) attn = operm @ Wo + bo  (M=8192,N=512,K=2048)
    split_trans<<<dim3(Dm / 32, 2048 / 32, 1), tb>>>(Wo, WoTh, WoTl, 2048, Dm, 0, 0);
    tcg(mk3(oph, opl, WoTh, WoTl), 3, attn, nullptr, nullptr,
        BSm, Dm, 2048, 2048, 2048, Dm, 0, 0, 0, 1, bo, 0, false);

    // 11) x2 = LN2(xd + attn), fused split
    ln_split<<<BSm, 128>>>(xd, attn, ln2g, ln2b, x2, x2h, x2l);

    // 12) mid = selu(x2 @ W1 + b1), epilogue writes bf16 split directly
    split_trans<<<dim3(MIDm / 32, Dm / 32, 1), tb>>>(W1, W1Th, W1Tl, Dm, MIDm, 0, 0);
    tcg(mk3(x2h, x2l, W1Th, W1Tl), 3, nullptr, midh, midl,
        BSm, MIDm, Dm, Dm, Dm, MIDm, 0, 0, 0, 1, b1, 0, true);

    // 13) ff = mid @ W2 + b2  (M=8192,N=512,K=2048)
    split_trans<<<dim3(Dm / 32, MIDm / 32, 1), tb>>>(W2, W2Th, W2Tl, MIDm, Dm, 0, 0);
    tcg(mk3(midh, midl, W2Th, W2Tl), 3, ff, nullptr, nullptr,
        BSm, Dm, MIDm, MIDm, MIDm, Dm, 0, 0, 0, 1, b2, 0, false);

    // 14) out = LN3(x2 + ff)
    ln_split<<<BSm, 128>>>(x2, ff, ln3g, ln3b, outp, nullptr, nullptr);
}

// round 5
// speedup vs baseline: 2.3233x; 1.1350x over previous
#include <cuda_runtime.h>
#include <cuda_bf16.h>
#include <math.h>
#include <stdint.h>

typedef __nv_bfloat16 bf16;

static constexpr int Dm = 512, Hn = 4, MIDm = 2048, Bm = 4, Sm = 2048;
static constexpr int BSm = Bm * Sm;                      // 8192
static constexpr long long BSD = (long long)BSm * Dm;    // 4194304
static constexpr long long SD  = (long long)Sm * Dm;     // 1048576
static constexpr long long DD  = (long long)Dm * Dm;     // 262144

// FFT-symmetry tile sizes
static constexpr int FR = 1152;   // rows computed (need 0..1024)
static constexpr int FC = 384;    // cols computed (need 0..256)
static constexpr int TN = 768;    // t12 width: 384 cos + 384 sin

// ---------------------------------------------------------------------------
// Static device scratch
// ---------------------------------------------------------------------------
__device__ __align__(256) bf16 g_CSh[FR * Sm], g_CSl[FR * Sm];
__device__ __align__(256) bf16 g_SSh[FR * Sm], g_SSl[FR * Sm];
__device__ __align__(256) bf16 g_BDh[TN * Dm], g_BDl[TN * Dm];
__device__ __align__(256) bf16 g_xdh[4194304], g_xdl[4194304];
__device__ __align__(256) bf16 g_xeh[4194304], g_xel[4194304];
__device__ __align__(256) float g_t12[BSm * TN];                   // [8192,768]
__device__ __align__(256) bf16 g_t12Th[4 * TN * Sm], g_t12Tl[4 * TN * Sm];
__device__ __align__(256) float g_cp[4 * FR * FC], g_sp[4 * FR * FC];
__device__ __align__(256) float g_xf[4194304];
__device__ __align__(256) float g_xd[4194304];
__device__ __align__(256) bf16 g_xdsh[4194304], g_xdsl[4194304];
__device__ __align__(256) float g_qs[16777216], g_ks[16777216];    // [h][b,s,d]
__device__ __align__(256) bf16 g_qsh[16777216], g_qsl[16777216];
__device__ __align__(256) bf16 g_ksTh[16777216], g_ksTl[16777216]; // [z][D,S]
__device__ __align__(256) bf16 g_vsTh[16777216], g_vsTl[16777216]; // [z][E,S]
__device__ __align__(256) bf16 g_gcTh[4194304], g_gcTl[4194304];   // [z][E,D]
__device__ __align__(256) bf16 g_oth[16777216], g_otl[16777216];   // [z][S,E]
__device__ __align__(256) bf16 g_WqTh[1048576], g_WqTl[1048576];
__device__ __align__(256) bf16 g_WkTh[1048576], g_WkTl[1048576];
__device__ __align__(256) bf16 g_WvTh[1048576], g_WvTl[1048576];
__device__ __align__(256) bf16 g_WoTh[1048576], g_WoTl[1048576];   // [h][512,512]
__device__ __align__(256) bf16 g_W1Th[1048576], g_W1Tl[1048576];   // [2048,512]
__device__ __align__(256) bf16 g_W2Th[1048576], g_W2Tl[1048576];   // [512,2048]
__device__ __align__(256) float g_attn[4194304];
__device__ __align__(256) float g_x2[4194304];
__device__ __align__(256) bf16 g_x2h[4194304], g_x2l[4194304];
__device__ __align__(256) bf16 g_midh[16777216], g_midl[16777216];
__device__ __align__(256) float g_ff[4194304];

// ---------------------------------------------------------------------------
// Helpers
// ---------------------------------------------------------------------------
__device__ __forceinline__ uint32_t smem_u32(const void* p) {
    uint32_t a;
    asm("{ .reg .u64 t; cvta.to.shared.u64 t, %1; cvt.u32.u64 %0, t; }" : "=r"(a) : "l"(p));
    return a;
}
__device__ __forceinline__ float selu_f(float x) {
    const float sc = 1.0507009873554805f, al = 1.6732632423543772f;
    return x > 0.f ? sc * x : sc * al * (expf(x) - 1.f);
}
__device__ __forceinline__ void split2(float x, bf16& h, bf16& l) {
    h = __float2bfloat16(x);
    l = __float2bfloat16(x - __bfloat162float(h));
}
__device__ __forceinline__ uint32_t packhl(bf16 a, bf16 b) {
    return ((uint32_t)*(uint16_t*)&b << 16) | (uint32_t)*(uint16_t*)&a;
}

#define LDSM_X4(r0, r1, r2, r3, addr) \
    asm volatile("ldmatrix.sync.aligned.m8n8.x4.shared.b16 {%0,%1,%2,%3}, [%4];" \
        : "=r"(r0), "=r"(r1), "=r"(r2), "=r"(r3) : "r"(addr))

#define MMA_BF16(d, a, b0, b1) \
    asm volatile("mma.sync.aligned.m16n8k16.row.col.f32.bf16.bf16.f32 " \
        "{%0,%1,%2,%3}, {%4,%5,%6,%7}, {%8,%9}, {%0,%1,%2,%3};" \
        : "+f"((d)[0]), "+f"((d)[1]), "+f"((d)[2]), "+f"((d)[3]) \
        : "r"((a)[0]), "r"((a)[1]), "r"((a)[2]), "r"((a)[3]), "r"(b0), "r"(b1))

#define CP_ASYNC16(dst, src) \
    asm volatile("cp.async.cg.shared.global [%0], [%1], 16;" :: "r"(dst), "l"(src))
#define CP_COMMIT() asm volatile("cp.async.commit_group;")
#define CP_WAIT1()  asm volatile("cp.async.wait_group 1;")

// ---------------------------------------------------------------------------
// HMMA GEMM, cp.async 3-stage pipeline, multi-pass accumulation.
// C[z] = sum_p A_p[z] @ B_p[z]^T (+bias col/row)(+SELU)(fp32 or bf16-split out)
// ---------------------------------------------------------------------------
struct TcPasses { const bf16* A[12]; const bf16* B[12]; };

static constexpr int BKg = 64;
static constexpr int LDSg = BKg + 8;
static constexpr int TILE_B = 128 * LDSg * 2;
static constexpr int STAGES = 3;
static constexpr int SMEM_B_OFF = STAGES * TILE_B;
static constexpr int SMEM_BIAS_OFF = 2 * STAGES * TILE_B;
static constexpr int SMEM_G = SMEM_BIAS_OFF + 128 * 4;

template <int ACT, int SPLIT, int BMODE>   // BMODE: 0 none, 1 col, 2 row
__global__ __launch_bounds__(256, 2) void mma_gemm(
    TcPasses P, int npass,
    float* __restrict__ C, bf16* __restrict__ Chi, bf16* __restrict__ Clo,
    int K, int lda, int ldb, int ldc,
    long long sA, long long sB, long long sC,
    const float* __restrict__ bias, long long sBias)
{
    extern __shared__ char smem[];
    float* bias_s = (float*)(smem + SMEM_BIAS_OFF);
    const uint32_t sA0 = smem_u32(smem);
    const uint32_t sB0 = sA0 + SMEM_B_OFF;

    const int tid = threadIdx.x;
    const int lane = tid & 31;
    const int wid = tid >> 5;
    const int wm = (wid & 1) * 64;
    const int wn = (wid >> 1) * 32;
    const int z = blockIdx.z;
    const int m0 = blockIdx.y * 128, n0 = blockIdx.x * 128;

    if (tid < 128) {
        if (BMODE == 0) bias_s[tid] = 0.f;
        else bias_s[tid] = bias[z * sBias + (BMODE == 2 ? m0 : n0) + tid];
    }

    float acc[4][4][4];
#pragma unroll
    for (int i = 0; i < 4; i++)
#pragma unroll
        for (int j = 0; j < 4; j++)
#pragma unroll
            for (int k = 0; k < 4; k++) acc[i][j][k] = 0.f;

    const int cpp = K / BKg;
    const int total = npass * cpp;

    const int crow = tid >> 3;
    const int ccol = (tid & 7) * 8;

    auto loadStage = [&](int c, int stg) {
        int p = c / cpp;
        int k0 = (c - p * cpp) * BKg;
        const bf16* Ab = P.A[p] + (long long)z * sA + k0 + ccol;
        const bf16* Bb = P.B[p] + (long long)z * sB + k0 + ccol;
        uint32_t da = sA0 + stg * TILE_B + (crow * LDSg + ccol) * 2;
        uint32_t db = sB0 + stg * TILE_B + (crow * LDSg + ccol) * 2;
#pragma unroll
        for (int i = 0; i < 4; i++) {
            int row = crow + i * 32;
            CP_ASYNC16(da + i * 32 * LDSg * 2, Ab + (long long)(m0 + row) * lda);
            CP_ASYNC16(db + i * 32 * LDSg * 2, Bb + (long long)(n0 + row) * ldb);
        }
    };

    loadStage(0, 0); CP_COMMIT();
    loadStage(1, 1); CP_COMMIT();

    const int lrow16 = lane & 15;
    const int lhalf = lane >> 4;

    for (int c = 0; c < total; c++) {
        CP_WAIT1();
        __syncthreads();
        const int stg = c % STAGES;
        const uint32_t aB = sA0 + stg * TILE_B;
        const uint32_t bB = sB0 + stg * TILE_B;
#pragma unroll
        for (int ks = 0; ks < 4; ks++) {
            uint32_t af[4][4];
#pragma unroll
            for (int mi = 0; mi < 4; mi++) {
                uint32_t addr = aB + (uint32_t)(((wm + mi * 16 + lrow16) * LDSg
                                                + ks * 16 + lhalf * 8) * 2);
                LDSM_X4(af[mi][0], af[mi][1], af[mi][2], af[mi][3], addr);
            }
            uint32_t bfr[2][4];
#pragma unroll
            for (int nj = 0; nj < 2; nj++) {
                uint32_t addr = bB + (uint32_t)(((wn + nj * 16 + lrow16) * LDSg
                                                + ks * 16 + lhalf * 8) * 2);
                LDSM_X4(bfr[nj][0], bfr[nj][1], bfr[nj][2], bfr[nj][3], addr);
            }
#pragma unroll
            for (int mi = 0; mi < 4; mi++)
#pragma unroll
                for (int ni = 0; ni < 4; ni++) {
                    const int nj = ni >> 1, sub = ni & 1;
                    MMA_BF16(acc[mi][ni], af[mi], bfr[nj][sub], bfr[nj][sub + 2]);
                }
        }
        if (c + 2 < total) loadStage(c + 2, (c + 2) % STAGES);
        CP_COMMIT();
    }

    const int cr = lane >> 2;
    const int cc = (lane & 3) * 2;
#pragma unroll
    for (int mi = 0; mi < 4; mi++) {
#pragma unroll
        for (int ni = 0; ni < 4; ni++) {
            const int bn = wn + ni * 8 + cc;
            const int gn = n0 + bn;
            const int rm = wm + mi * 16 + cr;
            const long long r0 = m0 + rm;
            const long long r1 = r0 + 8;
            float v0 = acc[mi][ni][0], v1 = acc[mi][ni][1];
            float v2 = acc[mi][ni][2], v3 = acc[mi][ni][3];
            if (BMODE == 1) {
                v0 += bias_s[bn]; v1 += bias_s[bn + 1];
                v2 += bias_s[bn]; v3 += bias_s[bn + 1];
            } else if (BMODE == 2) {
                v0 += bias_s[rm]; v1 += bias_s[rm];
                v2 += bias_s[rm + 8]; v3 += bias_s[rm + 8];
            }
            if (ACT == 1) { v0 = selu_f(v0); v1 = selu_f(v1); v2 = selu_f(v2); v3 = selu_f(v3); }
            if (SPLIT) {
                bf16 h0, l0, h1, l1;
                split2(v0, h0, l0); split2(v1, h1, l1);
                *(uint32_t*)(Chi + (long long)z * sC + r0 * ldc + gn) = packhl(h0, h1);
                *(uint32_t*)(Clo + (long long)z * sC + r0 * ldc + gn) = packhl(l0, l1);
                split2(v2, h0, l0); split2(v3, h1, l1);
                *(uint32_t*)(Chi + (long long)z * sC + r1 * ldc + gn) = packhl(h0, h1);
                *(uint32_t*)(Clo + (long long)z * sC + r1 * ldc + gn) = packhl(l0, l1);
            } else {
                *(float2*)(C + (long long)z * sC + r0 * ldc + gn) = make_float2(v0, v1);
                *(float2*)(C + (long long)z * sC + r1 * ldc + gn) = make_float2(v2, v3);
            }
        }
    }
}

// ---------------------------------------------------------------------------
// Elementwise kernels
// ---------------------------------------------------------------------------
// DFT rows [0,rows) of the NxN cos/sin matrices (positive sin).
__global__ void init_dft_rows(bf16* __restrict__ Ch, bf16* __restrict__ Cl,
                              bf16* __restrict__ Sh, bf16* __restrict__ Sl,
                              int rows, int N)
{
    long long idx = (long long)blockIdx.x * blockDim.x + threadIdx.x;
    if (idx >= (long long)rows * N) return;
    int i = (int)(idx / N), j = (int)(idx % N);
    int p = (int)(((long long)i * j) % N);
    float x = 2.0f * (float)p / (float)N;
    float s, c;
    sincospif(x, &s, &c);
    split2(c, Ch[idx], Cl[idx]);
    split2(s, Sh[idx], Sl[idx]);
}

// BD [TN,512]: rows 0..383 = cos rows, 384..767 = sin rows (D-axis DFT).
__global__ void init_bd(bf16* __restrict__ h, bf16* __restrict__ l)
{
    long long idx = (long long)blockIdx.x * blockDim.x + threadIdx.x;
    if (idx >= (long long)TN * Dm) return;
    int n = (int)(idx / Dm), k = (int)(idx % Dm);
    int i = (n < FC) ? n : (n - FC);
    int p = (int)(((long long)i * k) % Dm);
    float x = 2.0f * (float)p / (float)Dm;
    float s, c;
    sincospif(x, &s, &c);
    float v = (n < FC) ? c : s;
    split2(v, h[idx], l[idx]);
}

// vectorized split: 8 elems/thread
__global__ void split_k8(const float* __restrict__ in, bf16* __restrict__ h,
                         bf16* __restrict__ l, long long n8)
{
    long long i = (long long)blockIdx.x * blockDim.x + threadIdx.x;
    if (i >= n8) return;
    long long base = i * 8;
    float4 a = *(const float4*)(in + base);
    float4 b = *(const float4*)(in + base + 4);
    bf16 hh[8], ll[8];
    split2(a.x, hh[0], ll[0]); split2(a.y, hh[1], ll[1]);
    split2(a.z, hh[2], ll[2]); split2(a.w, hh[3], ll[3]);
    split2(b.x, hh[4], ll[4]); split2(b.y, hh[5], ll[5]);
    split2(b.z, hh[6], ll[6]); split2(b.w, hh[7], ll[7]);
    uint4 ho, lo;
    ho.x = packhl(hh[0], hh[1]); ho.y = packhl(hh[2], hh[3]);
    ho.z = packhl(hh[4], hh[5]); ho.w = packhl(hh[6], hh[7]);
    lo.x = packhl(ll[0], ll[1]); lo.y = packhl(ll[2], ll[3]);
    lo.z = packhl(ll[4], ll[5]); lo.w = packhl(ll[6], ll[7]);
    *(uint4*)(h + base) = ho;
    *(uint4*)(l + base) = lo;
}

// [R,C] fp32 -> [C,R] bf16 split, batched. grid (C/32, R/32, batch), block (32,8)
__global__ void split_trans(const float* __restrict__ in, bf16* __restrict__ oh,
                            bf16* __restrict__ ol, int R, int C,
                            long long sIn, long long sOut)
{
    __shared__ float t[32][33];
    const int z = blockIdx.z;
    const float* ib = in + (long long)z * sIn;
    const int c0 = blockIdx.x * 32, r0 = blockIdx.y * 32;
    const int tx = threadIdx.x, ty = threadIdx.y;
#pragma unroll
    for (int i = 0; i < 4; i++)
        t[ty + i * 8][tx] = ib[(long long)(r0 + ty + i * 8) * C + c0 + tx];
    __syncthreads();
#pragma unroll
    for (int i = 0; i < 4; i++) {
        float v = t[tx][ty + i * 8];
        long long o = (long long)z * sOut + (long long)(c0 + ty + i * 8) * R + r0 + tx;
        split2(v, oh[o], ol[o]);
    }
}

// Wo [2048,512] -> per-h transposed split: out[h][n,d] = Wo[d*4+h, n]
__global__ void wo_split_trans(const float* __restrict__ Wo, bf16* __restrict__ oh,
                               bf16* __restrict__ ol)
{
    __shared__ float t[32][33];
    const int h = blockIdx.z;
    const int n0 = blockIdx.x * 32, d0 = blockIdx.y * 32;
    const int tx = threadIdx.x, ty = threadIdx.y;
#pragma unroll
    for (int i = 0; i < 4; i++) {
        int d = d0 + ty + i * 8;
        t[ty + i * 8][tx] = Wo[(long long)(d * 4 + h) * Dm + n0 + tx];
    }
    __syncthreads();
#pragma unroll
    for (int i = 0; i < 4; i++) {
        float v = t[tx][ty + i * 8];
        long long o = (long long)h * DD + (long long)(n0 + ty + i * 8) * Dm + d0 + tx;
        split2(v, oh[o], ol[o]);
    }
}

// FFT quadrant reconstruction: xf from cpart/spart
__global__ void fft_merge(const float* __restrict__ cp, const float* __restrict__ sp,
                          float* __restrict__ xf)
{
    const int b = blockIdx.y;
    long long idx = (long long)blockIdx.x * blockDim.x + threadIdx.x;
    const long long TOT = 1025LL * 257LL;
    if (idx >= TOT) return;
    int i = (int)(idx / 257);
    int d = (int)(idx % 257);
    long long src = (long long)b * FR * FC + (long long)i * FC + d;
    float c = cp[src], s = sp[src];
    float a = c - s, bb = c + s;
    int i2 = (Sm - i) & (Sm - 1);
    int d2 = (Dm - d) & (Dm - 1);
    float* x = xf + (long long)b * SD;
    x[(long long)i * Dm + d] = a;
    x[(long long)i2 * Dm + d] = bb;
    x[(long long)i * Dm + d2] = bb;
    x[(long long)i2 * Dm + d2] = a;
}

// softmax over H=4 heads (stride BSD), split; 4 elems/thread
__global__ void softmax_split4(const float* __restrict__ q, bf16* __restrict__ oh,
                               bf16* __restrict__ ol)
{
    long long i4 = (long long)blockIdx.x * blockDim.x + threadIdx.x;
    if (i4 >= BSD / 4) return;
    long long base = i4 * 4;
    float4 v[4];
#pragma unroll
    for (int h = 0; h < 4; h++) v[h] = *(const float4*)(q + h * BSD + base);
    float r[4][4];
#pragma unroll
    for (int j = 0; j < 4; j++) {
        float a0 = ((const float*)&v[0])[j], a1 = ((const float*)&v[1])[j];
        float a2 = ((const float*)&v[2])[j], a3 = ((const float*)&v[3])[j];
        float m = fmaxf(fmaxf(a0, a1), fmaxf(a2, a3));
        float e0 = expf(a0 - m), e1 = expf(a1 - m), e2 = expf(a2 - m), e3 = expf(a3 - m);
        float inv = 1.f / (e0 + e1 + e2 + e3);
        r[0][j] = e0 * inv; r[1][j] = e1 * inv; r[2][j] = e2 * inv; r[3][j] = e3 * inv;
    }
#pragma unroll
    for (int h = 0; h < 4; h++) {
        bf16 hh[4], ll[4];
#pragma unroll
        for (int j = 0; j < 4; j++) split2(r[h][j], hh[j], ll[j]);
        uint2 ho = make_uint2(packhl(hh[0], hh[1]), packhl(hh[2], hh[3]));
        uint2 lo = make_uint2(packhl(ll[0], ll[1]), packhl(ll[2], ll[3]));
        *(uint2*)(oh + h * BSD + base) = ho;
        *(uint2*)(ol + h * BSD + base) = lo;
    }
}

// softmax over heads + transpose: ks[h][b][s,d] -> ksT[z=h*B+b][d,s] split.
__global__ void softmax_split_trans(const float* __restrict__ ks, bf16* __restrict__ oh,
                                    bf16* __restrict__ ol)
{
    __shared__ float t[4][32][33];
    const int b = blockIdx.z;
    const int s0 = blockIdx.x * 32, d0 = blockIdx.y * 32;
    const int tx = threadIdx.x, ty = threadIdx.y;
#pragma unroll
    for (int h = 0; h < 4; h++)
#pragma unroll
        for (int i = 0; i < 4; i++)
            t[h][ty + i * 8][tx] =
                ks[((long long)(h * Bm + b) * Sm + s0 + ty + i * 8) * Dm + d0 + tx];
    __syncthreads();
#pragma unroll
    for (int i = 0; i < 4; i++) {
        float v0 = t[0][ty + i * 8][tx], v1 = t[1][ty + i * 8][tx];
        float v2 = t[2][ty + i * 8][tx], v3 = t[3][ty + i * 8][tx];
        float m = fmaxf(fmaxf(v0, v1), fmaxf(v2, v3));
        float e0 = expf(v0 - m), e1 = expf(v1 - m), e2 = expf(v2 - m), e3 = expf(v3 - m);
        float r = 1.f / (e0 + e1 + e2 + e3);
        t[0][ty + i * 8][tx] = e0 * r; t[1][ty + i * 8][tx] = e1 * r;
        t[2][ty + i * 8][tx] = e2 * r; t[3][ty + i * 8][tx] = e3 * r;
    }
    __syncthreads();
#pragma unroll
    for (int h = 0; h < 4; h++)
#pragma unroll
        for (int i = 0; i < 4; i++) {
            float v = t[h][tx][ty + i * 8];
            long long o = (long long)(h * Bm + b) * SD + (long long)(d0 + ty + i * 8) * Sm + s0 + tx;
            split2(v, oh[o], ol[o]);
        }
}

// LN over last dim (D=512) of (a+b); optional split outputs.
__global__ void ln_split(const float* __restrict__ a, const float* __restrict__ bres,
                         const float* __restrict__ g, const float* __restrict__ be,
                         float* __restrict__ out, bf16* __restrict__ oh, bf16* __restrict__ ol)
{
    __shared__ float red[4];
    long long row = blockIdx.x;
    int t = threadIdx.x;  // 128
    float4 va = ((const float4*)(a + row * Dm))[t];
    float4 vb = ((const float4*)(bres + row * Dm))[t];
    float4 v = make_float4(va.x + vb.x, va.y + vb.y, va.z + vb.z, va.w + vb.w);
    float s = v.x + v.y + v.z + v.w;
#pragma unroll
    for (int o = 16; o > 0; o >>= 1) s += __shfl_xor_sync(0xffffffffu, s, o);
    if ((t & 31) == 0) red[t >> 5] = s;
    __syncthreads();
    float mu = (red[0] + red[1] + red[2] + red[3]) * (1.f / (float)Dm);
    __syncthreads();
    float d0 = v.x - mu, d1 = v.y - mu, d2 = v.z - mu, d3 = v.w - mu;
    float q = d0 * d0 + d1 * d1 + d2 * d2 + d3 * d3;
#pragma unroll
    for (int o = 16; o > 0; o >>= 1) q += __shfl_xor_sync(0xffffffffu, q, o);
    if ((t & 31) == 0) red[t >> 5] = q;
    __syncthreads();
    float var = (red[0] + red[1] + red[2] + red[3]) * (1.f / (float)Dm);
    float rstd = rsqrtf(var + 1e-5f);
    float4 vg = ((const float4*)g)[t];
    float4 vbe = ((const float4*)be)[t];
    float4 o4;
    o4.x = fmaf(vg.x, d0 * rstd, vbe.x);
    o4.y = fmaf(vg.y, d1 * rstd, vbe.y);
    o4.z = fmaf(vg.z, d2 * rstd, vbe.z);
    o4.w = fmaf(vg.w, d3 * rstd, vbe.w);
    ((float4*)(out + row * Dm))[t] = o4;
    if (oh) {
        long long o = row * Dm + t * 4;
        bf16 hh[4], ll[4];
        split2(o4.x, hh[0], ll[0]); split2(o4.y, hh[1], ll[1]);
        split2(o4.z, hh[2], ll[2]); split2(o4.w, hh[3], ll[3]);
        *(uint2*)(oh + o) = make_uint2(packhl(hh[0], hh[1]), packhl(hh[2], hh[3]));
        *(uint2*)(ol + o) = make_uint2(packhl(ll[0], ll[1]), packhl(ll[2], ll[3]));
    }
}

// ---------------------------------------------------------------------------
// Host
// ---------------------------------------------------------------------------
static TcPasses mk3(const bf16* Ah, const bf16* Al, const bf16* Bh, const bf16* Bl) {
    TcPasses P{};
    P.A[0] = Ah; P.B[0] = Bh;
    P.A[1] = Al; P.B[1] = Bh;
    P.A[2] = Ah; P.B[2] = Bl;
    return P;
}

static void tcg(const TcPasses& P, int np, float* C, bf16* Ch, bf16* Cl,
                int M, int N, int K, int lda, int ldb, int ldc,
                long long sA, long long sB, long long sC, int batch,
                const float* bias, long long sBias, int act, int split, int bmode)
{
    dim3 grid(N / 128, M / 128, batch), block(256);
    if (act == 1)
        mma_gemm<1, 1, 1><<<grid, block, SMEM_G>>>(P, np, C, Ch, Cl, K, lda, ldb, ldc, sA, sB, sC, bias, sBias);
    else if (split == 1 && bmode == 2)
        mma_gemm<0, 1, 2><<<grid, block, SMEM_G>>>(P, np, C, Ch, Cl, K, lda, ldb, ldc, sA, sB, sC, bias, sBias);
    else if (split == 1)
        mma_gemm<0, 1, 0><<<grid, block, SMEM_G>>>(P, np, C, Ch, Cl, K, lda, ldb, ldc, sA, sB, sC, bias, sBias);
    else if (bmode == 1)
        mma_gemm<0, 0, 1><<<grid, block, SMEM_G>>>(P, np, C, Ch, Cl, K, lda, ldb, ldc, sA, sB, sC, bias, sBias);
    else
        mma_gemm<0, 0, 0><<<grid, block, SMEM_G>>>(P, np, C, Ch, Cl, K, lda, ldb, ldc, sA, sB, sC, bias, sBias);
}

#define GETSYM(var, sym) do { void* _p; cudaGetSymbolAddress(&_p, sym); var = (decltype(var))_p; } while (0)

extern "C" void kernel_launch(void* const* d_in, const int* in_sizes, int n_in,
                              void* d_out, int out_size)
{
    const float* x_enc = (const float*)d_in[0];
    const float* x_dec = (const float*)d_in[1];
    const float* Wq = (const float*)d_in[2];
    const float* bq = (const float*)d_in[3];
    const float* Wk = (const float*)d_in[4];
    const float* bk = (const float*)d_in[5];
    const float* Wv = (const float*)d_in[6];
    const float* bv = (const float*)d_in[7];
    const float* Wo = (const float*)d_in[8];
    const float* bo = (const float*)d_in[9];
    const float* ln1g = (const float*)d_in[10];
    const float* ln1b = (const float*)d_in[11];
    const float* ln2g = (const float*)d_in[12];
    const float* ln2b = (const float*)d_in[13];
    const float* W1 = (const float*)d_in[14];
    const float* b1 = (const float*)d_in[15];
    const float* W2 = (const float*)d_in[16];
    const float* b2 = (const float*)d_in[17];
    const float* ln3g = (const float*)d_in[18];
    const float* ln3b = (const float*)d_in[19];
    float* outp = (float*)d_out;

    bf16 *CSh, *CSl, *SSh, *SSl, *BDh, *BDl;
    bf16 *xdh, *xdl, *xeh, *xel, *t12Th, *t12Tl, *xdsh, *xdsl;
    bf16 *qsh, *qsl, *ksTh, *ksTl, *vsTh, *vsTl, *gcTh, *gcTl, *oth, *otl;
    bf16 *WqTh, *WqTl, *WkTh, *WkTl, *WvTh, *WvTl, *WoTh, *WoTl, *W1Th, *W1Tl, *W2Th, *W2Tl;
    bf16 *x2h, *x2l, *midh, *midl;
    float *t12, *cp, *sp, *xf, *xd, *qs, *ks, *attn, *x2, *ff;
    GETSYM(CSh, g_CSh); GETSYM(CSl, g_CSl); GETSYM(SSh, g_SSh); GETSYM(SSl, g_SSl);
    GETSYM(BDh, g_BDh); GETSYM(BDl, g_BDl);
    GETSYM(xdh, g_xdh); GETSYM(xdl, g_xdl); GETSYM(xeh, g_xeh); GETSYM(xel, g_xel);
    GETSYM(t12, g_t12); GETSYM(t12Th, g_t12Th); GETSYM(t12Tl, g_t12Tl);
    GETSYM(cp, g_cp); GETSYM(sp, g_sp);
    GETSYM(xf, g_xf); GETSYM(xd, g_xd); GETSYM(xdsh, g_xdsh); GETSYM(xdsl, g_xdsl);
    GETSYM(qs, g_qs); GETSYM(ks, g_ks);
    GETSYM(qsh, g_qsh); GETSYM(qsl, g_qsl);
    GETSYM(ksTh, g_ksTh); GETSYM(ksTl, g_ksTl); GETSYM(vsTh, g_vsTh); GETSYM(vsTl, g_vsTl);
    GETSYM(gcTh, g_gcTh); GETSYM(gcTl, g_gcTl);
    GETSYM(oth, g_oth); GETSYM(otl, g_otl);
    GETSYM(WqTh, g_WqTh); GETSYM(WqTl, g_WqTl);
    GETSYM(WkTh, g_WkTh); GETSYM(WkTl, g_WkTl);
    GETSYM(WvTh, g_WvTh); GETSYM(WvTl, g_WvTl);
    GETSYM(WoTh, g_WoTh); GETSYM(WoTl, g_WoTl);
    GETSYM(W1Th, g_W1Th); GETSYM(W1Tl, g_W1Tl);
    GETSYM(W2Th, g_W2Th); GETSYM(W2Tl, g_W2Tl);
    GETSYM(attn, g_attn); GETSYM(x2, g_x2); GETSYM(x2h, g_x2h); GETSYM(x2l, g_x2l);
    GETSYM(midh, g_midh); GETSYM(midl, g_midl); GETSYM(ff, g_ff);

    cudaFuncSetAttribute(mma_gemm<0, 0, 0>, cudaFuncAttributeMaxDynamicSharedMemorySize, SMEM_G);
    cudaFuncSetAttribute(mma_gemm<0, 0, 1>, cudaFuncAttributeMaxDynamicSharedMemorySize, SMEM_G);
    cudaFuncSetAttribute(mma_gemm<0, 1, 0>, cudaFuncAttributeMaxDynamicSharedMemorySize, SMEM_G);
    cudaFuncSetAttribute(mma_gemm<0, 1, 2>, cudaFuncAttributeMaxDynamicSharedMemorySize, SMEM_G);
    cudaFuncSetAttribute(mma_gemm<1, 1, 1>, cudaFuncAttributeMaxDynamicSharedMemorySize, SMEM_G);

    dim3 tb(32, 8);

    // 0) DFT matrices
    init_dft_rows<<<(FR * Sm + 255) / 256, 256>>>(CSh, CSl, SSh, SSl, FR, Sm);
    init_bd<<<(TN * Dm + 255) / 256, 256>>>(BDh, BDl);

    // inputs split (vectorized)
    split_k8<<<(int)(BSD / 8 / 256), 256>>>(x_dec, xdh, xdl, BSD / 8);
    split_k8<<<(int)(BSD / 8 / 256), 256>>>(x_enc, xeh, xel, BSD / 8);

    // 1) t12 = x_dec @ BD^T  (M=8192, N=768, K=512)
    tcg(mk3(xdh, xdl, BDh, BDl), 3, t12, nullptr, nullptr,
        BSm, TN, Dm, Dm, Dm, TN, 0, 0, 0, 1, nullptr, 0, 0, 0, 0);
    // transpose per batch: [2048,768] -> [768,2048]
    split_trans<<<dim3(TN / 32, Sm / 32, Bm), tb>>>(t12, t12Th, t12Tl,
        Sm, TN, (long long)Sm * TN, (long long)TN * Sm);

    // 2) symmetric DFT parts: c = CS @ t1, s = SS @ t2  (M=1152,N=384,K=2048,z=4)
    tcg(mk3(CSh, CSl, t12Th, t12Tl), 3, cp, nullptr, nullptr,
        FR, FC, Sm, Sm, Sm, FC, 0, (long long)TN * Sm, (long long)FR * FC, Bm,
        nullptr, 0, 0, 0, 0);
    {
        const bf16* t2h = t12Th + (long long)FC * Sm;
        const bf16* t2l = t12Tl + (long long)FC * Sm;
        tcg(mk3(SSh, SSl, t2h, t2l), 3, sp, nullptr, nullptr,
            FR, FC, Sm, Sm, Sm, FC, 0, (long long)TN * Sm, (long long)FR * FC, Bm,
            nullptr, 0, 0, 0, 0);
    }
    // quadrant reconstruction
    fft_merge<<<dim3((1025 * 257 + 255) / 256, Bm), 256>>>(cp, sp, xf);

    // 3) xd = LN1(x_dec + xf), fused split
    ln_split<<<BSm, 128>>>(x_dec, xf, ln1g, ln1b, xd, xdsh, xdsl);

    // 4) weight transposes
    split_trans<<<dim3(16, 16, Hn), tb>>>(Wq, WqTh, WqTl, Dm, Dm, DD, DD);
    split_trans<<<dim3(16, 16, Hn), tb>>>(Wk, WkTh, WkTl, Dm, Dm, DD, DD);
    split_trans<<<dim3(16, 16, Hn), tb>>>(Wv, WvTh, WvTl, Dm, Dm, DD, DD);
    wo_split_trans<<<dim3(16, 16, Hn), tb>>>(Wo, WoTh, WoTl);
    split_trans<<<dim3(MIDm / 32, Dm / 32, 1), tb>>>(W1, W1Th, W1Tl, Dm, MIDm, 0, 0);
    split_trans<<<dim3(Dm / 32, MIDm / 32, 1), tb>>>(W2, W2Th, W2Tl, MIDm, Dm, 0, 0);

    // 5) q/k projections (fp32, col bias), z = head
    tcg(mk3(xdsh, xdsl, WqTh, WqTl), 3, qs, nullptr, nullptr,
        BSm, Dm, Dm, Dm, Dm, Dm, 0, DD, BSD, Hn, bq, Dm, 0, 0, 1);
    tcg(mk3(xeh, xel, WkTh, WkTl), 3, ks, nullptr, nullptr,
        BSm, Dm, Dm, Dm, Dm, Dm, 0, DD, BSD, Hn, bk, Dm, 0, 0, 1);

    // 6) vsT[h*B+b] = WvT_h @ x_enc[b]^T + bv_h (row bias), split direct
    for (int h = 0; h < Hn; h++) {
        tcg(mk3(WvTh + (long long)h * DD, WvTl + (long long)h * DD, xeh, xel),
            3, nullptr, vsTh + (long long)h * Bm * SD, vsTl + (long long)h * Bm * SD,
            Dm, Sm, Dm, Dm, Dm, Sm, 0, SD, SD, Bm, bv + (long long)h * Dm, 0, 0, 1, 2);
    }

    // 7) softmax over heads: q (in place layout), k (+transpose)
    softmax_split4<<<(int)(BSD / 4 / 256), 256>>>(qs, qsh, qsl);
    softmax_split_trans<<<dim3(Sm / 32, Dm / 32, Bm), tb>>>(ks, ksTh, ksTl);

    // 8) gcT[z] = vsT @ ksT^T  ([e,d]; M=N=512, K=2048, z=16), split direct
    tcg(mk3(vsTh, vsTl, ksTh, ksTl), 3, nullptr, gcTh, gcTl,
        Dm, Dm, Sm, Sm, Sm, Dm, SD, SD, DD, 16, nullptr, 0, 0, 1, 0);

    // 9) out[z] = qs @ gcT^T  ([s,e]; M=2048,N=512,K=512,z=16), split direct
    tcg(mk3(qsh, qsl, gcTh, gcTl), 3, nullptr, oth, otl,
        Sm, Dm, Dm, Dm, Dm, Dm, SD, DD, SD, 16, nullptr, 0, 0, 1, 0);

    // 10) attn[b] = sum_h out_h[b] @ WoT_h^T + bo  (12 passes; M=2048,N=512,K=512,z=4)
    {
        TcPasses P{};
        for (int h = 0; h < Hn; h++) {
            const bf16* Ah = oth + (long long)h * Bm * SD;
            const bf16* Al = otl + (long long)h * Bm * SD;
            const bf16* Bh = WoTh + (long long)h * DD;
            const bf16* Bl = WoTl + (long long)h * DD;
            P.A[h * 3 + 0] = Ah; P.B[h * 3 + 0] = Bh;
            P.A[h * 3 + 1] = Al; P.B[h * 3 + 1] = Bh;
            P.A[h * 3 + 2] = Ah; P.B[h * 3 + 2] = Bl;
        }
        tcg(P, 12, attn, nullptr, nullptr,
            Sm, Dm, Dm, Dm, Dm, Dm, SD, 0, SD, Bm, bo, 0, 0, 0, 1);
    }

    // 11) x2 = LN2(xd + attn), fused split
    ln_split<<<BSm, 128>>>(xd, attn, ln2g, ln2b, x2, x2h, x2l);

    // 12) mid = selu(x2 @ W1 + b1), split direct
    tcg(mk3(x2h, x2l, W1Th, W1Tl), 3, nullptr, midh, midl,
        BSm, MIDm, Dm, Dm, Dm, MIDm, 0, 0, 0, 1, b1, 0, 1, 1, 1);

    // 13) ff = mid @ W2 + b2
    tcg(mk3(midh, midl, W2Th, W2Tl), 3, ff, nullptr, nullptr,
        BSm, Dm, MIDm, MIDm, MIDm, Dm, 0, 0, 0, 1, b2, 0, 0, 0, 1);

    // 14) out = LN3(x2 + ff)
    ln_split<<<BSm, 128>>>(x2, ff, ln3g, ln3b, outp, nullptr, nullptr);
}

// round 6
// speedup vs baseline: 3.0898x; 1.3300x over previous
#include <cuda_runtime.h>
#include <cuda_fp16.h>
#include <math.h>
#include <stdint.h>

typedef __half hlf;

static constexpr int Dm = 512, Hn = 4, MIDm = 2048, Bm = 4, Sm = 2048;
static constexpr int BSm = Bm * Sm;                      // 8192
static constexpr long long BSD = (long long)BSm * Dm;    // 4194304
static constexpr long long SD  = (long long)Sm * Dm;     // 1048576
static constexpr long long DD  = (long long)Dm * Dm;     // 262144

// FFT-symmetry tile sizes
static constexpr int FR = 1152;   // rows computed (need 0..1024)
static constexpr int FC = 384;    // cols computed (need 0..256)
static constexpr int TN = 768;    // t12 width: 384 cos + 384 sin

// ---------------------------------------------------------------------------
// Static device scratch
// ---------------------------------------------------------------------------
__device__ __align__(256) hlf g_CSh[FR * Sm], g_CSl[FR * Sm];
__device__ __align__(256) hlf g_SSh[FR * Sm], g_SSl[FR * Sm];
__device__ __align__(256) hlf g_BDh[TN * Dm], g_BDl[TN * Dm];
__device__ __align__(256) hlf g_xdh[4194304], g_xdl[4194304];
__device__ __align__(256) hlf g_xeh[4194304], g_xel[4194304];
__device__ __align__(256) float g_t12[BSm * TN];                   // [8192,768]
__device__ __align__(256) hlf g_t12Th[4 * TN * Sm], g_t12Tl[4 * TN * Sm];
__device__ __align__(256) float g_cp[4 * FR * FC], g_sp[4 * FR * FC];
__device__ __align__(256) float g_xf[4194304];
__device__ __align__(256) float g_xd[4194304];
__device__ __align__(256) hlf g_xdsh[4194304], g_xdsl[4194304];
__device__ __align__(256) float g_qs[16777216], g_ks[16777216];    // [h][b,s,d]
__device__ __align__(256) hlf g_qsh[16777216], g_qsl[16777216];
__device__ __align__(256) hlf g_ksTh[16777216], g_ksTl[16777216];  // [z][D,S]
__device__ __align__(256) hlf g_vsTh[16777216], g_vsTl[16777216];  // [z][E,S]
__device__ __align__(256) hlf g_gcTh[4194304], g_gcTl[4194304];    // [z][E,D]
__device__ __align__(256) hlf g_oth[16777216], g_otl[16777216];    // [z][S,E]
__device__ __align__(256) hlf g_WqTh[1048576], g_WqTl[1048576];
__device__ __align__(256) hlf g_WkTh[1048576], g_WkTl[1048576];
__device__ __align__(256) hlf g_WvTh[1048576], g_WvTl[1048576];
__device__ __align__(256) hlf g_WoTh[1048576], g_WoTl[1048576];    // [h][512,512]
__device__ __align__(256) hlf g_W1Th[1048576], g_W1Tl[1048576];    // [2048,512]
__device__ __align__(256) hlf g_W2Th[1048576], g_W2Tl[1048576];    // [512,2048]
__device__ __align__(256) float g_attn[4194304];
__device__ __align__(256) float g_x2[4194304];
__device__ __align__(256) hlf g_x2h[4194304], g_x2l[4194304];
__device__ __align__(256) hlf g_midh[16777216], g_midl[16777216];
__device__ __align__(256) float g_ff[4194304];

// ---------------------------------------------------------------------------
// Helpers
// ---------------------------------------------------------------------------
__device__ __forceinline__ uint32_t smem_u32(const void* p) {
    uint32_t a;
    asm("{ .reg .u64 t; cvta.to.shared.u64 t, %1; cvt.u32.u64 %0, t; }" : "=r"(a) : "l"(p));
    return a;
}
__device__ __forceinline__ float selu_f(float x) {
    const float sc = 1.0507009873554805f, al = 1.6732632423543772f;
    return x > 0.f ? sc * x : sc * al * (expf(x) - 1.f);
}
__device__ __forceinline__ void split2(float x, hlf& h, hlf& l) {
    h = __float2half_rn(x);
    l = __float2half_rn(x - __half2float(h));
}
__device__ __forceinline__ uint32_t packhl(hlf a, hlf b) {
    return ((uint32_t)*(uint16_t*)&b << 16) | (uint32_t)*(uint16_t*)&a;
}

#define LDSM_X4(r0, r1, r2, r3, addr) \
    asm volatile("ldmatrix.sync.aligned.m8n8.x4.shared.b16 {%0,%1,%2,%3}, [%4];" \
        : "=r"(r0), "=r"(r1), "=r"(r2), "=r"(r3) : "r"(addr))

#define MMA_F16(d, a, b0, b1) \
    asm volatile("mma.sync.aligned.m16n8k16.row.col.f32.f16.f16.f32 " \
        "{%0,%1,%2,%3}, {%4,%5,%6,%7}, {%8,%9}, {%0,%1,%2,%3};" \
        : "+f"((d)[0]), "+f"((d)[1]), "+f"((d)[2]), "+f"((d)[3]) \
        : "r"((a)[0]), "r"((a)[1]), "r"((a)[2]), "r"((a)[3]), "r"(b0), "r"(b1))

#define CP_ASYNC16(dst, src) \
    asm volatile("cp.async.cg.shared.global [%0], [%1], 16;" :: "r"(dst), "l"(src))
#define CP_COMMIT() asm volatile("cp.async.commit_group;")
#define CP_WAIT1()  asm volatile("cp.async.wait_group 1;")

// ---------------------------------------------------------------------------
// HMMA GEMM, cp.async 3-stage pipeline, multi-pass accumulation.
// C[z] = sum_p A_p[z>>shA] @ B_p[z&mskB]^T (+bias col/row)(+SELU)
// (fp32 or fp16-split out)
// ---------------------------------------------------------------------------
struct TcPasses { const hlf* A[12]; const hlf* B[12]; };

static constexpr int BKg = 64;
static constexpr int LDSg = BKg + 8;
static constexpr int TILE_B = 128 * LDSg * 2;
static constexpr int STAGES = 3;
static constexpr int SMEM_B_OFF = STAGES * TILE_B;
static constexpr int SMEM_BIAS_OFF = 2 * STAGES * TILE_B;
static constexpr int SMEM_G = SMEM_BIAS_OFF + 128 * 4;

template <int ACT, int SPLIT, int BMODE>   // BMODE: 0 none, 1 col, 2 row
__global__ __launch_bounds__(256, 2) void mma_gemm(
    TcPasses P, int npass,
    float* __restrict__ C, hlf* __restrict__ Chi, hlf* __restrict__ Clo,
    int K, int lda, int ldb, int ldc,
    long long sA, long long sB, long long sC,
    const float* __restrict__ bias, long long sBias,
    int shA, int mskB)
{
    extern __shared__ char smem[];
    float* bias_s = (float*)(smem + SMEM_BIAS_OFF);
    const uint32_t sA0 = smem_u32(smem);
    const uint32_t sB0 = sA0 + SMEM_B_OFF;

    const int tid = threadIdx.x;
    const int lane = tid & 31;
    const int wid = tid >> 5;
    const int wm = (wid & 1) * 64;
    const int wn = (wid >> 1) * 32;
    const int z = blockIdx.z;
    const int za = z >> shA;
    const int zb = z & mskB;
    const int m0 = blockIdx.y * 128, n0 = blockIdx.x * 128;

    if (tid < 128) {
        if (BMODE == 0) bias_s[tid] = 0.f;
        else bias_s[tid] = bias[(long long)za * sBias + (BMODE == 2 ? m0 : n0) + tid];
    }

    float acc[4][4][4];
#pragma unroll
    for (int i = 0; i < 4; i++)
#pragma unroll
        for (int j = 0; j < 4; j++)
#pragma unroll
            for (int k = 0; k < 4; k++) acc[i][j][k] = 0.f;

    const int cpp = K / BKg;
    const int total = npass * cpp;

    const int crow = tid >> 3;
    const int ccol = (tid & 7) * 8;

    auto loadStage = [&](int c, int stg) {
        int p = c / cpp;
        int k0 = (c - p * cpp) * BKg;
        const hlf* Ab = P.A[p] + (long long)za * sA + k0 + ccol;
        const hlf* Bb = P.B[p] + (long long)zb * sB + k0 + ccol;
        uint32_t da = sA0 + stg * TILE_B + (crow * LDSg + ccol) * 2;
        uint32_t db = sB0 + stg * TILE_B + (crow * LDSg + ccol) * 2;
#pragma unroll
        for (int i = 0; i < 4; i++) {
            int row = crow + i * 32;
            CP_ASYNC16(da + i * 32 * LDSg * 2, Ab + (long long)(m0 + row) * lda);
            CP_ASYNC16(db + i * 32 * LDSg * 2, Bb + (long long)(n0 + row) * ldb);
        }
    };

    loadStage(0, 0); CP_COMMIT();
    loadStage(1, 1); CP_COMMIT();

    const int lrow16 = lane & 15;
    const int lhalf = lane >> 4;

    for (int c = 0; c < total; c++) {
        CP_WAIT1();
        __syncthreads();
        const int stg = c % STAGES;
        const uint32_t aB = sA0 + stg * TILE_B;
        const uint32_t bB = sB0 + stg * TILE_B;
#pragma unroll
        for (int ks = 0; ks < 4; ks++) {
            uint32_t af[4][4];
#pragma unroll
            for (int mi = 0; mi < 4; mi++) {
                uint32_t addr = aB + (uint32_t)(((wm + mi * 16 + lrow16) * LDSg
                                                + ks * 16 + lhalf * 8) * 2);
                LDSM_X4(af[mi][0], af[mi][1], af[mi][2], af[mi][3], addr);
            }
            uint32_t bfr[2][4];
#pragma unroll
            for (int nj = 0; nj < 2; nj++) {
                uint32_t addr = bB + (uint32_t)(((wn + nj * 16 + lrow16) * LDSg
                                                + ks * 16 + lhalf * 8) * 2);
                LDSM_X4(bfr[nj][0], bfr[nj][1], bfr[nj][2], bfr[nj][3], addr);
            }
#pragma unroll
            for (int mi = 0; mi < 4; mi++)
#pragma unroll
                for (int ni = 0; ni < 4; ni++) {
                    const int nj = ni >> 1, sub = ni & 1;
                    MMA_F16(acc[mi][ni], af[mi], bfr[nj][sub], bfr[nj][sub + 2]);
                }
        }
        if (c + 2 < total) loadStage(c + 2, (c + 2) % STAGES);
        CP_COMMIT();
    }

    const int cr = lane >> 2;
    const int cc = (lane & 3) * 2;
#pragma unroll
    for (int mi = 0; mi < 4; mi++) {
#pragma unroll
        for (int ni = 0; ni < 4; ni++) {
            const int bn = wn + ni * 8 + cc;
            const int gn = n0 + bn;
            const int rm = wm + mi * 16 + cr;
            const long long r0 = m0 + rm;
            const long long r1 = r0 + 8;
            float v0 = acc[mi][ni][0], v1 = acc[mi][ni][1];
            float v2 = acc[mi][ni][2], v3 = acc[mi][ni][3];
            if (BMODE == 1) {
                v0 += bias_s[bn]; v1 += bias_s[bn + 1];
                v2 += bias_s[bn]; v3 += bias_s[bn + 1];
            } else if (BMODE == 2) {
                v0 += bias_s[rm]; v1 += bias_s[rm];
                v2 += bias_s[rm + 8]; v3 += bias_s[rm + 8];
            }
            if (ACT == 1) { v0 = selu_f(v0); v1 = selu_f(v1); v2 = selu_f(v2); v3 = selu_f(v3); }
            if (SPLIT) {
                hlf h0, l0, h1, l1;
                split2(v0, h0, l0); split2(v1, h1, l1);
                *(uint32_t*)(Chi + (long long)z * sC + r0 * ldc + gn) = packhl(h0, h1);
                *(uint32_t*)(Clo + (long long)z * sC + r0 * ldc + gn) = packhl(l0, l1);
                split2(v2, h0, l0); split2(v3, h1, l1);
                *(uint32_t*)(Chi + (long long)z * sC + r1 * ldc + gn) = packhl(h0, h1);
                *(uint32_t*)(Clo + (long long)z * sC + r1 * ldc + gn) = packhl(l0, l1);
            } else {
                *(float2*)(C + (long long)z * sC + r0 * ldc + gn) = make_float2(v0, v1);
                *(float2*)(C + (long long)z * sC + r1 * ldc + gn) = make_float2(v2, v3);
            }
        }
    }
}

// ---------------------------------------------------------------------------
// Elementwise kernels
// ---------------------------------------------------------------------------
__global__ void init_dft_rows(hlf* __restrict__ Ch, hlf* __restrict__ Cl,
                              hlf* __restrict__ Sh, hlf* __restrict__ Sl,
                              int rows, int N)
{
    long long idx = (long long)blockIdx.x * blockDim.x + threadIdx.x;
    if (idx >= (long long)rows * N) return;
    int i = (int)(idx / N), j = (int)(idx % N);
    int p = (int)(((long long)i * j) % N);
    float x = 2.0f * (float)p / (float)N;
    float s, c;
    sincospif(x, &s, &c);
    split2(c, Ch[idx], Cl[idx]);
    split2(s, Sh[idx], Sl[idx]);
}

__global__ void init_bd(hlf* __restrict__ h, hlf* __restrict__ l)
{
    long long idx = (long long)blockIdx.x * blockDim.x + threadIdx.x;
    if (idx >= (long long)TN * Dm) return;
    int n = (int)(idx / Dm), k = (int)(idx % Dm);
    int i = (n < FC) ? n : (n - FC);
    int p = (int)(((long long)i * k) % Dm);
    float x = 2.0f * (float)p / (float)Dm;
    float s, c;
    sincospif(x, &s, &c);
    float v = (n < FC) ? c : s;
    split2(v, h[idx], l[idx]);
}

__global__ void split_k8(const float* __restrict__ in, hlf* __restrict__ h,
                         hlf* __restrict__ l, long long n8)
{
    long long i = (long long)blockIdx.x * blockDim.x + threadIdx.x;
    if (i >= n8) return;
    long long base = i * 8;
    float4 a = *(const float4*)(in + base);
    float4 b = *(const float4*)(in + base + 4);
    hlf hh[8], ll[8];
    split2(a.x, hh[0], ll[0]); split2(a.y, hh[1], ll[1]);
    split2(a.z, hh[2], ll[2]); split2(a.w, hh[3], ll[3]);
    split2(b.x, hh[4], ll[4]); split2(b.y, hh[5], ll[5]);
    split2(b.z, hh[6], ll[6]); split2(b.w, hh[7], ll[7]);
    uint4 ho, lo;
    ho.x = packhl(hh[0], hh[1]); ho.y = packhl(hh[2], hh[3]);
    ho.z = packhl(hh[4], hh[5]); ho.w = packhl(hh[6], hh[7]);
    lo.x = packhl(ll[0], ll[1]); lo.y = packhl(ll[2], ll[3]);
    lo.z = packhl(ll[4], ll[5]); lo.w = packhl(ll[6], ll[7]);
    *(uint4*)(h + base) = ho;
    *(uint4*)(l + base) = lo;
}

// [R,C] fp32 -> [C,R] fp16 split, batched. grid (C/32, R/32, batch), block (32,8)
__global__ void split_trans(const float* __restrict__ in, hlf* __restrict__ oh,
                            hlf* __restrict__ ol, int R, int C,
                            long long sIn, long long sOut)
{
    __shared__ float t[32][33];
    const int z = blockIdx.z;
    const float* ib = in + (long long)z * sIn;
    const int c0 = blockIdx.x * 32, r0 = blockIdx.y * 32;
    const int tx = threadIdx.x, ty = threadIdx.y;
#pragma unroll
    for (int i = 0; i < 4; i++)
        t[ty + i * 8][tx] = ib[(long long)(r0 + ty + i * 8) * C + c0 + tx];
    __syncthreads();
#pragma unroll
    for (int i = 0; i < 4; i++) {
        float v = t[tx][ty + i * 8];
        long long o = (long long)z * sOut + (long long)(c0 + ty + i * 8) * R + r0 + tx;
        split2(v, oh[o], ol[o]);
    }
}

// Wo [2048,512] -> per-h transposed split: out[h][n,d] = Wo[d*4+h, n]
__global__ void wo_split_trans(const float* __restrict__ Wo, hlf* __restrict__ oh,
                               hlf* __restrict__ ol)
{
    __shared__ float t[32][33];
    const int h = blockIdx.z;
    const int n0 = blockIdx.x * 32, d0 = blockIdx.y * 32;
    const int tx = threadIdx.x, ty = threadIdx.y;
#pragma unroll
    for (int i = 0; i < 4; i++) {
        int d = d0 + ty + i * 8;
        t[ty + i * 8][tx] = Wo[(long long)(d * 4 + h) * Dm + n0 + tx];
    }
    __syncthreads();
#pragma unroll
    for (int i = 0; i < 4; i++) {
        float v = t[tx][ty + i * 8];
        long long o = (long long)h * DD + (long long)(n0 + ty + i * 8) * Dm + d0 + tx;
        split2(v, oh[o], ol[o]);
    }
}

// FFT quadrant reconstruction
__global__ void fft_merge(const float* __restrict__ cp, const float* __restrict__ sp,
                          float* __restrict__ xf)
{
    const int b = blockIdx.y;
    long long idx = (long long)blockIdx.x * blockDim.x + threadIdx.x;
    const long long TOT = 1025LL * 257LL;
    if (idx >= TOT) return;
    int i = (int)(idx / 257);
    int d = (int)(idx % 257);
    long long src = (long long)b * FR * FC + (long long)i * FC + d;
    float c = cp[src], s = sp[src];
    float a = c - s, bb = c + s;
    int i2 = (Sm - i) & (Sm - 1);
    int d2 = (Dm - d) & (Dm - 1);
    float* x = xf + (long long)b * SD;
    x[(long long)i * Dm + d] = a;
    x[(long long)i2 * Dm + d] = bb;
    x[(long long)i * Dm + d2] = bb;
    x[(long long)i2 * Dm + d2] = a;
}

// softmax over H=4 heads (stride BSD), split; 4 elems/thread
__global__ void softmax_split4(const float* __restrict__ q, hlf* __restrict__ oh,
                               hlf* __restrict__ ol)
{
    long long i4 = (long long)blockIdx.x * blockDim.x + threadIdx.x;
    if (i4 >= BSD / 4) return;
    long long base = i4 * 4;
    float4 v[4];
#pragma unroll
    for (int h = 0; h < 4; h++) v[h] = *(const float4*)(q + h * BSD + base);
    float r[4][4];
#pragma unroll
    for (int j = 0; j < 4; j++) {
        float a0 = ((const float*)&v[0])[j], a1 = ((const float*)&v[1])[j];
        float a2 = ((const float*)&v[2])[j], a3 = ((const float*)&v[3])[j];
        float m = fmaxf(fmaxf(a0, a1), fmaxf(a2, a3));
        float e0 = expf(a0 - m), e1 = expf(a1 - m), e2 = expf(a2 - m), e3 = expf(a3 - m);
        float inv = 1.f / (e0 + e1 + e2 + e3);
        r[0][j] = e0 * inv; r[1][j] = e1 * inv; r[2][j] = e2 * inv; r[3][j] = e3 * inv;
    }
#pragma unroll
    for (int h = 0; h < 4; h++) {
        hlf hh[4], ll[4];
#pragma unroll
        for (int j = 0; j < 4; j++) split2(r[h][j], hh[j], ll[j]);
        uint2 ho = make_uint2(packhl(hh[0], hh[1]), packhl(hh[2], hh[3]));
        uint2 lo = make_uint2(packhl(ll[0], ll[1]), packhl(ll[2], ll[3]));
        *(uint2*)(oh + h * BSD + base) = ho;
        *(uint2*)(ol + h * BSD + base) = lo;
    }
}

// softmax over heads + transpose: ks[h][b][s,d] -> ksT[z=h*B+b][d,s] split.
__global__ void softmax_split_trans(const float* __restrict__ ks, hlf* __restrict__ oh,
                                    hlf* __restrict__ ol)
{
    __shared__ float t[4][32][33];
    const int b = blockIdx.z;
    const int s0 = blockIdx.x * 32, d0 = blockIdx.y * 32;
    const int tx = threadIdx.x, ty = threadIdx.y;
#pragma unroll
    for (int h = 0; h < 4; h++)
#pragma unroll
        for (int i = 0; i < 4; i++)
            t[h][ty + i * 8][tx] =
                ks[((long long)(h * Bm + b) * Sm + s0 + ty + i * 8) * Dm + d0 + tx];
    __syncthreads();
#pragma unroll
    for (int i = 0; i < 4; i++) {
        float v0 = t[0][ty + i * 8][tx], v1 = t[1][ty + i * 8][tx];
        float v2 = t[2][ty + i * 8][tx], v3 = t[3][ty + i * 8][tx];
        float m = fmaxf(fmaxf(v0, v1), fmaxf(v2, v3));
        float e0 = expf(v0 - m), e1 = expf(v1 - m), e2 = expf(v2 - m), e3 = expf(v3 - m);
        float r = 1.f / (e0 + e1 + e2 + e3);
        t[0][ty + i * 8][tx] = e0 * r; t[1][ty + i * 8][tx] = e1 * r;
        t[2][ty + i * 8][tx] = e2 * r; t[3][ty + i * 8][tx] = e3 * r;
    }
    __syncthreads();
#pragma unroll
    for (int h = 0; h < 4; h++)
#pragma unroll
        for (int i = 0; i < 4; i++) {
            float v = t[h][tx][ty + i * 8];
            long long o = (long long)(h * Bm + b) * SD + (long long)(d0 + ty + i * 8) * Sm + s0 + tx;
            split2(v, oh[o], ol[o]);
        }
}

// LN over last dim (D=512) of (a+b); optional split outputs.
__global__ void ln_split(const float* __restrict__ a, const float* __restrict__ bres,
                         const float* __restrict__ g, const float* __restrict__ be,
                         float* __restrict__ out, hlf* __restrict__ oh, hlf* __restrict__ ol)
{
    __shared__ float red[4];
    long long row = blockIdx.x;
    int t = threadIdx.x;  // 128
    float4 va = ((const float4*)(a + row * Dm))[t];
    float4 vb = ((const float4*)(bres + row * Dm))[t];
    float4 v = make_float4(va.x + vb.x, va.y + vb.y, va.z + vb.z, va.w + vb.w);
    float s = v.x + v.y + v.z + v.w;
#pragma unroll
    for (int o = 16; o > 0; o >>= 1) s += __shfl_xor_sync(0xffffffffu, s, o);
    if ((t & 31) == 0) red[t >> 5] = s;
    __syncthreads();
    float mu = (red[0] + red[1] + red[2] + red[3]) * (1.f / (float)Dm);
    __syncthreads();
    float d0 = v.x - mu, d1 = v.y - mu, d2 = v.z - mu, d3 = v.w - mu;
    float q = d0 * d0 + d1 * d1 + d2 * d2 + d3 * d3;
#pragma unroll
    for (int o = 16; o > 0; o >>= 1) q += __shfl_xor_sync(0xffffffffu, q, o);
    if ((t & 31) == 0) red[t >> 5] = q;
    __syncthreads();
    float var = (red[0] + red[1] + red[2] + red[3]) * (1.f / (float)Dm);
    float rstd = rsqrtf(var + 1e-5f);
    float4 vg = ((const float4*)g)[t];
    float4 vbe = ((const float4*)be)[t];
    float4 o4;
    o4.x = fmaf(vg.x, d0 * rstd, vbe.x);
    o4.y = fmaf(vg.y, d1 * rstd, vbe.y);
    o4.z = fmaf(vg.z, d2 * rstd, vbe.z);
    o4.w = fmaf(vg.w, d3 * rstd, vbe.w);
    ((float4*)(out + row * Dm))[t] = o4;
    if (oh) {
        long long o = row * Dm + t * 4;
        hlf hh[4], ll[4];
        split2(o4.x, hh[0], ll[0]); split2(o4.y, hh[1], ll[1]);
        split2(o4.z, hh[2], ll[2]); split2(o4.w, hh[3], ll[3]);
        *(uint2*)(oh + o) = make_uint2(packhl(hh[0], hh[1]), packhl(hh[2], hh[3]));
        *(uint2*)(ol + o) = make_uint2(packhl(ll[0], ll[1]), packhl(ll[2], ll[3]));
    }
}

// ---------------------------------------------------------------------------
// Host
// ---------------------------------------------------------------------------
static TcPasses mk3(const hlf* Ah, const hlf* Al, const hlf* Bh, const hlf* Bl) {
    TcPasses P{};
    P.A[0] = Ah; P.B[0] = Bh;
    P.A[1] = Al; P.B[1] = Bh;
    P.A[2] = Ah; P.B[2] = Bl;
    return P;
}
static TcPasses mk2(const hlf* Ah, const hlf* Al, const hlf* Bh) {
    TcPasses P{};
    P.A[0] = Ah; P.B[0] = Bh;
    P.A[1] = Al; P.B[1] = Bh;
    return P;
}

static void tcg(const TcPasses& P, int np, float* C, hlf* Ch, hlf* Cl,
                int M, int N, int K, int lda, int ldb, int ldc,
                long long sA, long long sB, long long sC, int batch,
                const float* bias, long long sBias, int act, int split, int bmode,
                int shA = 0, int mskB = 0x7FFFFFFF)
{
    dim3 grid(N / 128, M / 128, batch), block(256);
    if (act == 1)
        mma_gemm<1, 1, 1><<<grid, block, SMEM_G>>>(P, np, C, Ch, Cl, K, lda, ldb, ldc, sA, sB, sC, bias, sBias, shA, mskB);
    else if (split == 1 && bmode == 2)
        mma_gemm<0, 1, 2><<<grid, block, SMEM_G>>>(P, np, C, Ch, Cl, K, lda, ldb, ldc, sA, sB, sC, bias, sBias, shA, mskB);
    else if (split == 1)
        mma_gemm<0, 1, 0><<<grid, block, SMEM_G>>>(P, np, C, Ch, Cl, K, lda, ldb, ldc, sA, sB, sC, bias, sBias, shA, mskB);
    else if (bmode == 1)
        mma_gemm<0, 0, 1><<<grid, block, SMEM_G>>>(P, np, C, Ch, Cl, K, lda, ldb, ldc, sA, sB, sC, bias, sBias, shA, mskB);
    else
        mma_gemm<0, 0, 0><<<grid, block, SMEM_G>>>(P, np, C, Ch, Cl, K, lda, ldb, ldc, sA, sB, sC, bias, sBias, shA, mskB);
}

#define GETSYM(var, sym) do { void* _p; cudaGetSymbolAddress(&_p, sym); var = (decltype(var))_p; } while (0)

extern "C" void kernel_launch(void* const* d_in, const int* in_sizes, int n_in,
                              void* d_out, int out_size)
{
    const float* x_enc = (const float*)d_in[0];
    const float* x_dec = (const float*)d_in[1];
    const float* Wq = (const float*)d_in[2];
    const float* bq = (const float*)d_in[3];
    const float* Wk = (const float*)d_in[4];
    const float* bk = (const float*)d_in[5];
    const float* Wv = (const float*)d_in[6];
    const float* bv = (const float*)d_in[7];
    const float* Wo = (const float*)d_in[8];
    const float* bo = (const float*)d_in[9];
    const float* ln1g = (const float*)d_in[10];
    const float* ln1b = (const float*)d_in[11];
    const float* ln2g = (const float*)d_in[12];
    const float* ln2b = (const float*)d_in[13];
    const float* W1 = (const float*)d_in[14];
    const float* b1 = (const float*)d_in[15];
    const float* W2 = (const float*)d_in[16];
    const float* b2 = (const float*)d_in[17];
    const float* ln3g = (const float*)d_in[18];
    const float* ln3b = (const float*)d_in[19];
    float* outp = (float*)d_out;

    hlf *CSh, *CSl, *SSh, *SSl, *BDh, *BDl;
    hlf *xdh, *xdl, *xeh, *xel, *t12Th, *t12Tl, *xdsh, *xdsl;
    hlf *qsh, *qsl, *ksTh, *ksTl, *vsTh, *vsTl, *gcTh, *gcTl, *oth, *otl;
    hlf *WqTh, *WqTl, *WkTh, *WkTl, *WvTh, *WvTl, *WoTh, *WoTl, *W1Th, *W1Tl, *W2Th, *W2Tl;
    hlf *x2h, *x2l, *midh, *midl;
    float *t12, *cp, *sp, *xf, *xd, *qs, *ks, *attn, *x2, *ff;
    GETSYM(CSh, g_CSh); GETSYM(CSl, g_CSl); GETSYM(SSh, g_SSh); GETSYM(SSl, g_SSl);
    GETSYM(BDh, g_BDh); GETSYM(BDl, g_BDl);
    GETSYM(xdh, g_xdh); GETSYM(xdl, g_xdl); GETSYM(xeh, g_xeh); GETSYM(xel, g_xel);
    GETSYM(t12, g_t12); GETSYM(t12Th, g_t12Th); GETSYM(t12Tl, g_t12Tl);
    GETSYM(cp, g_cp); GETSYM(sp, g_sp);
    GETSYM(xf, g_xf); GETSYM(xd, g_xd); GETSYM(xdsh, g_xdsh); GETSYM(xdsl, g_xdsl);
    GETSYM(qs, g_qs); GETSYM(ks, g_ks);
    GETSYM(qsh, g_qsh); GETSYM(qsl, g_qsl);
    GETSYM(ksTh, g_ksTh); GETSYM(ksTl, g_ksTl); GETSYM(vsTh, g_vsTh); GETSYM(vsTl, g_vsTl);
    GETSYM(gcTh, g_gcTh); GETSYM(gcTl, g_gcTl);
    GETSYM(oth, g_oth); GETSYM(otl, g_otl);
    GETSYM(WqTh, g_WqTh); GETSYM(WqTl, g_WqTl);
    GETSYM(WkTh, g_WkTh); GETSYM(WkTl, g_WkTl);
    GETSYM(WvTh, g_WvTh); GETSYM(WvTl, g_WvTl);
    GETSYM(WoTh, g_WoTh); GETSYM(WoTl, g_WoTl);
    GETSYM(W1Th, g_W1Th); GETSYM(W1Tl, g_W1Tl);
    GETSYM(W2Th, g_W2Th); GETSYM(W2Tl, g_W2Tl);
    GETSYM(attn, g_attn); GETSYM(x2, g_x2); GETSYM(x2h, g_x2h); GETSYM(x2l, g_x2l);
    GETSYM(midh, g_midh); GETSYM(midl, g_midl); GETSYM(ff, g_ff);

    cudaFuncSetAttribute(mma_gemm<0, 0, 0>, cudaFuncAttributeMaxDynamicSharedMemorySize, SMEM_G);
    cudaFuncSetAttribute(mma_gemm<0, 0, 1>, cudaFuncAttributeMaxDynamicSharedMemorySize, SMEM_G);
    cudaFuncSetAttribute(mma_gemm<0, 1, 0>, cudaFuncAttributeMaxDynamicSharedMemorySize, SMEM_G);
    cudaFuncSetAttribute(mma_gemm<0, 1, 2>, cudaFuncAttributeMaxDynamicSharedMemorySize, SMEM_G);
    cudaFuncSetAttribute(mma_gemm<1, 1, 1>, cudaFuncAttributeMaxDynamicSharedMemorySize, SMEM_G);

    dim3 tb(32, 8);

    // 0) DFT matrices
    init_dft_rows<<<(FR * Sm + 255) / 256, 256>>>(CSh, CSl, SSh, SSl, FR, Sm);
    init_bd<<<(TN * Dm + 255) / 256, 256>>>(BDh, BDl);

    // inputs split (vectorized)
    split_k8<<<(int)(BSD / 8 / 256), 256>>>(x_dec, xdh, xdl, BSD / 8);
    split_k8<<<(int)(BSD / 8 / 256), 256>>>(x_enc, xeh, xel, BSD / 8);

    // 1) t12 = x_dec @ BD^T  (M=8192, N=768, K=512) -- 3-pass (FFT chain)
    tcg(mk3(xdh, xdl, BDh, BDl), 3, t12, nullptr, nullptr,
        BSm, TN, Dm, Dm, Dm, TN, 0, 0, 0, 1, nullptr, 0, 0, 0, 0);
    split_trans<<<dim3(TN / 32, Sm / 32, Bm), tb>>>(t12, t12Th, t12Tl,
        Sm, TN, (long long)Sm * TN, (long long)TN * Sm);

    // 2) symmetric DFT parts: c = CS @ t1, s = SS @ t2 -- 3-pass
    tcg(mk3(CSh, CSl, t12Th, t12Tl), 3, cp, nullptr, nullptr,
        FR, FC, Sm, Sm, Sm, FC, 0, (long long)TN * Sm, (long long)FR * FC, Bm,
        nullptr, 0, 0, 0, 0);
    {
        const hlf* t2h = t12Th + (long long)FC * Sm;
        const hlf* t2l = t12Tl + (long long)FC * Sm;
        tcg(mk3(SSh, SSl, t2h, t2l), 3, sp, nullptr, nullptr,
            FR, FC, Sm, Sm, Sm, FC, 0, (long long)TN * Sm, (long long)FR * FC, Bm,
            nullptr, 0, 0, 0, 0);
    }
    fft_merge<<<dim3((1025 * 257 + 255) / 256, Bm), 256>>>(cp, sp, xf);

    // 3) xd = LN1(x_dec + xf), fused split
    ln_split<<<BSm, 128>>>(x_dec, xf, ln1g, ln1b, xd, xdsh, xdsl);

    // 4) weight transposes
    split_trans<<<dim3(16, 16, Hn), tb>>>(Wq, WqTh, WqTl, Dm, Dm, DD, DD);
    split_trans<<<dim3(16, 16, Hn), tb>>>(Wk, WkTh, WkTl, Dm, Dm, DD, DD);
    split_trans<<<dim3(16, 16, Hn), tb>>>(Wv, WvTh, WvTl, Dm, Dm, DD, DD);
    wo_split_trans<<<dim3(16, 16, Hn), tb>>>(Wo, WoTh, WoTl);
    split_trans<<<dim3(MIDm / 32, Dm / 32, 1), tb>>>(W1, W1Th, W1Tl, Dm, MIDm, 0, 0);
    split_trans<<<dim3(Dm / 32, MIDm / 32, 1), tb>>>(W2, W2Th, W2Tl, MIDm, Dm, 0, 0);

    // 5) q/k projections (fp32, col bias), z = head -- 2-pass
    tcg(mk2(xdsh, xdsl, WqTh), 2, qs, nullptr, nullptr,
        BSm, Dm, Dm, Dm, Dm, Dm, 0, DD, BSD, Hn, bq, Dm, 0, 0, 1);
    tcg(mk2(xeh, xel, WkTh), 2, ks, nullptr, nullptr,
        BSm, Dm, Dm, Dm, Dm, Dm, 0, DD, BSD, Hn, bk, Dm, 0, 0, 1);

    // 6) vsT[z=h*4+b] = WvT_h @ x_enc[b]^T + bv_h (row bias), split direct; z=16
    tcg(mk2(WvTh, WvTl, xeh), 2, nullptr, vsTh, vsTl,
        Dm, Sm, Dm, Dm, Dm, Sm, DD, SD, SD, 16, bv, Dm, 0, 1, 2,
        /*shA=*/2, /*mskB=*/3);

    // 7) softmax over heads: q, k (+transpose)
    softmax_split4<<<(int)(BSD / 4 / 256), 256>>>(qs, qsh, qsl);
    softmax_split_trans<<<dim3(Sm / 32, Dm / 32, Bm), tb>>>(ks, ksTh, ksTl);

    // 8) gcT[z] = vsT @ ksT^T  ([e,d]; M=N=512, K=2048, z=16) -- 2-pass
    tcg(mk2(vsTh, vsTl, ksTh), 2, nullptr, gcTh, gcTl,
        Dm, Dm, Sm, Sm, Sm, Dm, SD, SD, DD, 16, nullptr, 0, 0, 1, 0);

    // 9) out[z] = qs @ gcT^T  ([s,e]; M=2048,N=512,K=512,z=16) -- 2-pass
    tcg(mk2(qsh, qsl, gcTh), 2, nullptr, oth, otl,
        Sm, Dm, Dm, Dm, Dm, Dm, SD, DD, SD, 16, nullptr, 0, 0, 1, 0);

    // 10) attn[b] = sum_h out_h[b] @ WoT_h^T + bo  (8 passes; M=2048,N=512,K=512,z=4)
    {
        TcPasses P{};
        for (int h = 0; h < Hn; h++) {
            const hlf* Ah = oth + (long long)h * Bm * SD;
            const hlf* Al = otl + (long long)h * Bm * SD;
            const hlf* Bh = WoTh + (long long)h * DD;
            P.A[h * 2 + 0] = Ah; P.B[h * 2 + 0] = Bh;
            P.A[h * 2 + 1] = Al; P.B[h * 2 + 1] = Bh;
        }
        tcg(P, 8, attn, nullptr, nullptr,
            Sm, Dm, Dm, Dm, Dm, Dm, SD, 0, SD, Bm, bo, 0, 0, 0, 1);
    }

    // 11) x2 = LN2(xd + attn), fused split
    ln_split<<<BSm, 128>>>(xd, attn, ln2g, ln2b, x2, x2h, x2l);

    // 12) mid = selu(x2 @ W1 + b1), split direct -- 2-pass
    tcg(mk2(x2h, x2l, W1Th), 2, nullptr, midh, midl,
        BSm, MIDm, Dm, Dm, Dm, MIDm, 0, 0, 0, 1, b1, 0, 1, 1, 1);

    // 13) ff = mid @ W2 + b2 -- 2-pass
    tcg(mk2(midh, midl, W2Th), 2, ff, nullptr, nullptr,
        BSm, Dm, MIDm, MIDm, MIDm, Dm, 0, 0, 0, 1, b2, 0, 0, 0, 1);

    // 14) out = LN3(x2 + ff)
    ln_split<<<BSm, 128>>>(x2, ff, ln3g, ln3b, outp, nullptr, nullptr);
}